// round 11
// baseline (speedup 1.0000x reference)
#include <cuda_runtime.h>
#include <cuda_fp16.h>
#include <math.h>
#include <stdint.h>

// ---------------------------------------------------------------------------
// Problem constants
// ---------------------------------------------------------------------------
#define BATCH     4
#define TLEN      4096
#define MTOK      (BATCH * TLEN)      // 16384 tokens
#define DIM       1024
#define DINNER    2048
#define DSTATE    16
#define KCONV     4
#define SSM_R     32

// ---------------------------------------------------------------------------
// Scratch buffers (static device globals; no allocation anywhere)
// ---------------------------------------------------------------------------
__device__ float  g_xin  [(size_t)MTOK * DINNER];
__device__ __half g_gate_h[(size_t)MTOK * DINNER];
__device__ float  g_xs1  [(size_t)(MTOK/2) * DINNER];
__device__ float  g_xs2  [(size_t)(MTOK/4) * DINNER];
__device__ float  g_y0   [(size_t)MTOK     * DINNER];
__device__ float  g_y1   [(size_t)(MTOK/2) * DINNER];
__device__ float  g_y2   [(size_t)(MTOK/4) * DINNER];
__device__ __half g_fusedpre_h[(size_t)MTOK * DINNER];
__device__ __half g_x_h    [(size_t)MTOK * DIM];
__device__ __half g_ctx_h  [(size_t)MTOK * DINNER];
__device__ __half g_h_h    [(size_t)MTOK * (DINNER/2)];
__device__ __half g_fused_h[(size_t)MTOK * DINNER];
__device__ __half g_wTh  [(size_t)(DIM*2*DINNER) + (size_t)(DINNER*(DINNER/2))
                          + (size_t)((DINNER/2)*DINNER) + (size_t)(DINNER*DIM)];

// ---------------------------------------------------------------------------
// Math helpers
// ---------------------------------------------------------------------------
__device__ __forceinline__ float sigmoidf_(float x) { return 1.0f / (1.0f + expf(-x)); }
__device__ __forceinline__ float siluf_(float x)    { return x / (1.0f + expf(-x)); }
__device__ __forceinline__ float softplusf_(float x) {
    return x > 0.0f ? x + log1pf(expf(-x)) : log1pf(expf(x));
}

// ---------------------------------------------------------------------------
// PTX helpers
// ---------------------------------------------------------------------------
__device__ __forceinline__ uint32_t smem_u32(const void* p) {
    uint32_t a;
    asm("{ .reg .u64 t; cvta.to.shared.u64 t, %1; cvt.u32.u64 %0, t; }" : "=r"(a) : "l"(p));
    return a;
}
__device__ __forceinline__ void cp_async16(uint32_t saddr, const void* gaddr) {
    asm volatile("cp.async.cg.shared.global [%0], [%1], 16;"
                 :: "r"(saddr), "l"(gaddr) : "memory");
}
#define CP_COMMIT() asm volatile("cp.async.commit_group;" ::: "memory")
#define CP_WAIT(n)  asm volatile("cp.async.wait_group %0;" :: "n"(n) : "memory")

__device__ __forceinline__ void ldsm_x4(uint32_t* r, uint32_t addr) {
    asm volatile("ldmatrix.sync.aligned.m8n8.x4.shared.b16 {%0,%1,%2,%3}, [%4];"
                 : "=r"(r[0]), "=r"(r[1]), "=r"(r[2]), "=r"(r[3]) : "r"(addr));
}
__device__ __forceinline__ void mma_f16(float* d, const uint32_t* a, const uint32_t* b) {
    asm volatile(
        "mma.sync.aligned.m16n8k16.row.col.f32.f16.f16.f32 "
        "{%0,%1,%2,%3}, {%4,%5,%6,%7}, {%8,%9}, {%0,%1,%2,%3};"
        : "+f"(d[0]), "+f"(d[1]), "+f"(d[2]), "+f"(d[3])
        : "r"(a[0]), "r"(a[1]), "r"(a[2]), "r"(a[3]), "r"(b[0]), "r"(b[1]));
}

// ---------------------------------------------------------------------------
// FP16 tensor-core GEMM v2: C[M,N] = A[M,K] @ Bt[N,K]^T, fp32 accumulate.
// Block tile 256x128, 8 warps (4x2), warp tile 64x64. 1 CTA/SM (smem-bound).
// 3-stage cp.async. Per k16 step: 8 ldmatrix.x4 feed 32 MMAs.
// EPI: 1 silu->half, 2 cg-combine->half, 3 +residual->f32,
//      4 split x_in f32 | silu(gate) half
// ---------------------------------------------------------------------------
#define STAGES   3
#define BMT      256
#define BNT      128
#define A_TILEB  (BMT * 128)          // 32768
#define B_TILEB  (BNT * 128)          // 16384
#define STAGE_B  (A_TILEB + B_TILEB)  // 49152
#define SM_TOTAL2 (STAGES * STAGE_B)  // 147456

template <int EPI>
__global__ __launch_bounds__(256, 1)
void tgemm_kernel(const __half* __restrict__ A, const __half* __restrict__ Bt,
                  void* __restrict__ Cv, int M, int N, int K,
                  const float* __restrict__ aux, const __half* __restrict__ aux2h,
                  __half* __restrict__ auxh)
{
    extern __shared__ char smem[];
    const uint32_t sbase = smem_u32(smem);
    const int tid = threadIdx.x;
    const int lid = tid & 31;
    const int wid = tid >> 5;
    const int warp_m = wid >> 1;      // 0..3  (64-row slabs)
    const int warp_n = wid & 1;       // 0..1  (64-col slabs)
    const int bn = blockIdx.x, bm = blockIdx.y;

    const __half* Abase = A  + (size_t)bm * BMT * K;
    const __half* Bbase = Bt + (size_t)bn * BNT * K;
    const int nk = K >> 6;

    auto issue_copy = [&](int chunk, int buf) {
        const int k0 = chunk << 6;
        const int u  = tid & 7;
        const uint32_t sa = sbase + buf * STAGE_B;
        const uint32_t sb = sa + A_TILEB;
#pragma unroll
        for (int i = 0; i < 8; i++) {         // A: 256 rows
            const int r = (tid >> 3) + i * 32;
            const uint32_t so = (uint32_t)(r * 128 + ((u ^ (r & 7)) << 4));
            cp_async16(sa + so, Abase + (size_t)r * K + k0 + u * 8);
        }
#pragma unroll
        for (int i = 0; i < 4; i++) {         // B: 128 rows
            const int r = (tid >> 3) + i * 32;
            const uint32_t so = (uint32_t)(r * 128 + ((u ^ (r & 7)) << 4));
            cp_async16(sb + so, Bbase + (size_t)r * K + k0 + u * 8);
        }
        CP_COMMIT();
    };

    float acc[4][8][4];
#pragma unroll
    for (int i = 0; i < 4; i++)
#pragma unroll
        for (int j = 0; j < 8; j++)
#pragma unroll
            for (int c = 0; c < 4; c++) acc[i][j][c] = 0.0f;

    issue_copy(0, 0);
    if (nk > 1) issue_copy(1, 1);

    for (int it = 0; it < nk; ++it) {
        if (it + 2 < nk) { issue_copy(it + 2, (it + 2) % STAGES); CP_WAIT(2); }
        else if (it + 1 < nk) { CP_WAIT(1); }
        else { CP_WAIT(0); }
        __syncthreads();

        const uint32_t a_s = sbase + (it % STAGES) * STAGE_B;
        const uint32_t b_s = a_s + A_TILEB;

#pragma unroll
        for (int ks = 0; ks < 4; ks++) {
            const int ub = ks * 2;
            uint32_t af[4][4];
#pragma unroll
            for (int mf = 0; mf < 4; mf++) {
                const int row  = warp_m * 64 + mf * 16 + (lid & 15);
                const int unit = ub + (lid >> 4);
                ldsm_x4(af[mf], a_s + (uint32_t)(row * 128 + ((unit ^ (row & 7)) << 4)));
            }
            uint32_t bf[8][2];
#pragma unroll
            for (int p = 0; p < 4; p++) {
                const int row  = warp_n * 64 + p * 16 + ((lid >> 4) & 1) * 8 + (lid & 7);
                const int unit = ub + ((lid >> 3) & 1);
                uint32_t t[4];
                ldsm_x4(t, b_s + (uint32_t)(row * 128 + ((unit ^ (row & 7)) << 4)));
                bf[p * 2][0] = t[0]; bf[p * 2][1] = t[1];
                bf[p * 2 + 1][0] = t[2]; bf[p * 2 + 1][1] = t[3];
            }
#pragma unroll
            for (int mf = 0; mf < 4; mf++)
#pragma unroll
                for (int nf = 0; nf < 8; nf++)
                    mma_f16(acc[mf][nf], af[mf], bf[nf]);
        }
        __syncthreads();
    }

    // Epilogue
#pragma unroll
    for (int mf = 0; mf < 4; mf++)
#pragma unroll
        for (int nf = 0; nf < 8; nf++)
#pragma unroll
            for (int hh = 0; hh < 2; hh++) {
                const int row = bm * BMT + warp_m * 64 + mf * 16 + (lid >> 2) + hh * 8;
                const int col = bn * BNT + warp_n * 64 + nf * 8 + (lid & 3) * 2;
                float2 v = make_float2(acc[mf][nf][hh * 2], acc[mf][nf][hh * 2 + 1]);
                const size_t idx = (size_t)row * N + col;
                if (EPI == 1) {
                    *(__half2*)((__half*)Cv + idx) =
                        __floats2half2_rn(siluf_(v.x), siluf_(v.y));
                } else if (EPI == 2) {
                    const float2 f  = __half22float2(*(const __half2*)(aux2h + idx));
                    const float2 gt = __half22float2(*(const __half2*)(auxh + idx));
                    const float ox = f.x * sigmoidf_(v.x) * gt.x;
                    const float oy = f.y * sigmoidf_(v.y) * gt.y;
                    *(__half2*)((__half*)Cv + idx) = __floats2half2_rn(ox, oy);
                } else if (EPI == 3) {
                    const float2 rr = *(const float2*)(aux + idx);
                    v.x += rr.x; v.y += rr.y;
                    *(float2*)((float*)Cv + idx) = v;
                } else { // EPI == 4
                    if (col < DINNER) {
                        *(float2*)((float*)Cv + (size_t)row * DINNER + col) = v;
                    } else {
                        *(__half2*)(auxh + (size_t)row * DINNER + (col - DINNER)) =
                            __floats2half2_rn(siluf_(v.x), siluf_(v.y));
                    }
                }
            }
}

// ---------------------------------------------------------------------------
// fp32 -> fp16 convert
// ---------------------------------------------------------------------------
__global__ void f2h_kernel(const float* __restrict__ in, __half* __restrict__ out,
                           int n4)
{
    const int i = blockIdx.x * 256 + threadIdx.x;
    if (i < n4) {
        const float4 v = *(const float4*)(in + (size_t)i * 4);
        ((__half2*)out)[(size_t)i * 2]     = __floats2half2_rn(v.x, v.y);
        ((__half2*)out)[(size_t)i * 2 + 1] = __floats2half2_rn(v.z, v.w);
    }
}

// ---------------------------------------------------------------------------
// Weight transpose: in[K,N] fp32 -> out[N,K] fp16
// ---------------------------------------------------------------------------
__global__ void transpose_kernel(const float* __restrict__ in, __half* __restrict__ out,
                                 int K, int N)
{
    __shared__ float t[32][33];
    const int n0 = blockIdx.x * 32, k0 = blockIdx.y * 32;
    const int tx = threadIdx.x, ty = threadIdx.y;
#pragma unroll
    for (int i = 0; i < 32; i += 8)
        t[ty + i][tx] = in[(size_t)(k0 + ty + i) * N + n0 + tx];
    __syncthreads();
#pragma unroll
    for (int i = 0; i < 32; i += 8)
        out[(size_t)(n0 + ty + i) * K + k0 + tx] = __float2half(t[tx][ty + i]);
}

// ---------------------------------------------------------------------------
// Downsample (mean pooling over time, factor 2 or 4) from x_in
// ---------------------------------------------------------------------------
__global__ void down_kernel(const float* __restrict__ xin, float* __restrict__ out,
                            int factor, int Tout)
{
    const int r = blockIdx.x;
    const int b = r / Tout, t = r % Tout;
    const float inv = 1.0f / (float)factor;
    const size_t srow = ((size_t)b * TLEN + (size_t)t * factor) * DINNER;
    for (int c4 = threadIdx.x; c4 < DINNER / 4; c4 += 256) {
        const int c = c4 * 4;
        float4 s = make_float4(0.f, 0.f, 0.f, 0.f);
        for (int k = 0; k < factor; k++) {
            const float4 v = *(const float4*)(xin + srow + (size_t)k * DINNER + c);
            s.x += v.x; s.y += v.y; s.z += v.z; s.w += v.w;
        }
        s.x *= inv; s.y *= inv; s.z *= inv; s.w *= inv;
        *(float4*)(out + (size_t)r * DINNER + c) = s;
    }
}

// ---------------------------------------------------------------------------
// Fused SSM core v2 (unchanged from R7 win)
// ---------------------------------------------------------------------------
#define SSM_SMEM (DINNER * DSTATE * 2 * 2)   // 131072

__global__ __launch_bounds__(256)
void ssm2_kernel(const float* __restrict__ X,
                 const float* __restrict__ cw,
                 const float* __restrict__ cb,
                 const float* __restrict__ xw,
                 const float* __restrict__ dtw,
                 const float* __restrict__ dtb,
                 const float* __restrict__ Dp,
                 float* __restrict__ y, int Ts)
{
    extern __shared__ __half sh[];
    __half* s_xw  = sh;
    __half* s_dtw = sh + DINNER * DSTATE;
    __shared__ float s_wp[8][16];
    __shared__ float s_B[DSTATE];

    const int tid = threadIdx.x;
    const int lane = tid & 31, warp = tid >> 5;
    const int c0 = tid * 8;
    const int r0 = blockIdx.x * SSM_R;
    const int trow0 = r0 % Ts;

    for (int idx = tid; idx < DINNER * DSTATE; idx += 256) {
        const int c = idx >> 4, j = idx & 15;
        s_xw[idx] = __float2half(xw[c * (2 * DSTATE) + j]);
    }
    for (int idx = tid; idx < DSTATE * DINNER; idx += 256)
        s_dtw[idx] = __float2half(dtw[idx]);

    float4 cw4[8];
#pragma unroll
    for (int i = 0; i < 8; i++) cw4[i] = *(const float4*)(cw + (size_t)(c0 + i) * 4);
    float cbv[8], dtbv[8], Dv[8];
    {
        const float4 a = *(const float4*)(cb + c0);
        const float4 b = *(const float4*)(cb + c0 + 4);
        cbv[0]=a.x; cbv[1]=a.y; cbv[2]=a.z; cbv[3]=a.w;
        cbv[4]=b.x; cbv[5]=b.y; cbv[6]=b.z; cbv[7]=b.w;
        const float4 c1 = *(const float4*)(dtb + c0);
        const float4 c2 = *(const float4*)(dtb + c0 + 4);
        dtbv[0]=c1.x; dtbv[1]=c1.y; dtbv[2]=c1.z; dtbv[3]=c1.w;
        dtbv[4]=c2.x; dtbv[5]=c2.y; dtbv[6]=c2.z; dtbv[7]=c2.w;
        const float4 d1 = *(const float4*)(Dp + c0);
        const float4 d2 = *(const float4*)(Dp + c0 + 4);
        Dv[0]=d1.x; Dv[1]=d1.y; Dv[2]=d1.z; Dv[3]=d1.w;
        Dv[4]=d2.x; Dv[5]=d2.y; Dv[6]=d2.z; Dv[7]=d2.w;
    }

    auto loadrow = [&](int row, float* v) {
        const float4 a = *(const float4*)(X + (size_t)row * DINNER + c0);
        const float4 b = *(const float4*)(X + (size_t)row * DINNER + c0 + 4);
        v[0]=a.x; v[1]=a.y; v[2]=a.z; v[3]=a.w;
        v[4]=b.x; v[5]=b.y; v[6]=b.z; v[7]=b.w;
    };

    float w0[8], w1[8], w2[8], cur[8];
    if (trow0 == 0) {
#pragma unroll
        for (int i = 0; i < 8; i++) { w0[i] = 0.f; w1[i] = 0.f; w2[i] = 0.f; }
    } else {
        loadrow(r0 - 3, w0);
        loadrow(r0 - 2, w1);
        loadrow(r0 - 1, w2);
    }
    __syncthreads();

    for (int r = 0; r < SSM_R; r++) {
        const int row = r0 + r;
        loadrow(row, cur);

        float xc[8];
#pragma unroll
        for (int i = 0; i < 8; i++) {
            const float a = cbv[i] + cw4[i].x * w0[i] + cw4[i].y * w1[i]
                          + cw4[i].z * w2[i] + cw4[i].w * cur[i];
            xc[i] = siluf_(a);
        }

        float part[16];
#pragma unroll
        for (int j = 0; j < 16; j++) part[j] = 0.0f;
#pragma unroll
        for (int i = 0; i < 8; i++) {
            const __half2* p = (const __half2*)&s_xw[(c0 + i) * 16];
            const float xi = xc[i];
#pragma unroll
            for (int j2 = 0; j2 < 8; j2++) {
                const float2 f = __half22float2(p[j2]);
                part[j2 * 2]     += xi * f.x;
                part[j2 * 2 + 1] += xi * f.y;
            }
        }
#pragma unroll
        for (int j = 0; j < 16; j++)
#pragma unroll
            for (int o = 16; o; o >>= 1)
                part[j] += __shfl_xor_sync(0xffffffffu, part[j], o);
        if (lane == 0) {
#pragma unroll
            for (int j = 0; j < 16; j++) s_wp[warp][j] = part[j];
        }
        __syncthreads();
        if (tid < 16) {
            float s = 0.0f;
#pragma unroll
            for (int w = 0; w < 8; w++) s += s_wp[w][tid];
            s_B[tid] = s;
        }
        __syncthreads();

        float lo[8];
#pragma unroll
        for (int i = 0; i < 8; i++) lo[i] = dtbv[i];
#pragma unroll
        for (int j = 0; j < DSTATE; j++) {
            const float bj = s_B[j];
            const __half2* p = (const __half2*)&s_dtw[j * DINNER + c0];
#pragma unroll
            for (int i2 = 0; i2 < 4; i2++) {
                const float2 f = __half22float2(p[i2]);
                lo[i2 * 2]     += bj * f.x;
                lo[i2 * 2 + 1] += bj * f.y;
            }
        }
        float yv[8];
#pragma unroll
        for (int i = 0; i < 8; i++)
            yv[i] = xc[i] * sigmoidf_(softplusf_(lo[i])) + Dv[i] * cur[i];
        *(float4*)(y + (size_t)row * DINNER + c0)     = make_float4(yv[0], yv[1], yv[2], yv[3]);
        *(float4*)(y + (size_t)row * DINNER + c0 + 4) = make_float4(yv[4], yv[5], yv[6], yv[7]);

#pragma unroll
        for (int i = 0; i < 8; i++) { w0[i] = w1[i]; w1[i] = w2[i]; w2[i] = cur[i]; }
        __syncthreads();
    }
}

// ---------------------------------------------------------------------------
// Linear upsample + softmax-weighted mix + ctx (both half)
// ---------------------------------------------------------------------------
__global__ void mix_kernel(const float* __restrict__ y0,
                           const float* __restrict__ y1,
                           const float* __restrict__ y2,
                           const float* __restrict__ sw,
                           __half* __restrict__ fused_pre_h,
                           __half* __restrict__ ctx_h)
{
    const int r = blockIdx.x;
    const int b = r >> 12, t = r & (TLEN - 1);

    const float s0 = sw[0], s1 = sw[1], s2 = sw[2];
    const float m  = fmaxf(s0, fmaxf(s1, s2));
    const float e0 = expf(s0 - m), e1 = expf(s1 - m), e2 = expf(s2 - m);
    const float inv = 1.0f / (e0 + e1 + e2);
    const float w0 = e0 * inv, w1 = e1 * inv, w2 = e2 * inv;

    float c1 = fminf(fmaxf((t + 0.5f) * 0.5f - 0.5f, 0.0f), (float)(TLEN / 2 - 1));
    int lo1 = (int)floorf(c1);
    int hi1 = min(lo1 + 1, TLEN / 2 - 1);
    float f1 = c1 - (float)lo1;

    float c2 = fminf(fmaxf((t + 0.5f) * 0.25f - 0.5f, 0.0f), (float)(TLEN / 4 - 1));
    int lo2 = (int)floorf(c2);
    int hi2 = min(lo2 + 1, TLEN / 4 - 1);
    float f2 = c2 - (float)lo2;

    const float* p0  = y0 + (size_t)r * DINNER;
    const float* p1a = y1 + ((size_t)(b * (TLEN / 2) + lo1)) * DINNER;
    const float* p1b = y1 + ((size_t)(b * (TLEN / 2) + hi1)) * DINNER;
    const float* p2a = y2 + ((size_t)(b * (TLEN / 4) + lo2)) * DINNER;
    const float* p2b = y2 + ((size_t)(b * (TLEN / 4) + hi2)) * DINNER;

    for (int c = threadIdx.x * 2; c < DINNER; c += 512) {
        const float2 v0  = *(const float2*)(p0 + c);
        const float2 a1  = *(const float2*)(p1a + c);
        const float2 b1v = *(const float2*)(p1b + c);
        const float2 a2  = *(const float2*)(p2a + c);
        const float2 b2v = *(const float2*)(p2b + c);
        const float u1x = a1.x * (1.0f - f1) + b1v.x * f1;
        const float u1y = a1.y * (1.0f - f1) + b1v.y * f1;
        const float u2x = a2.x * (1.0f - f2) + b2v.x * f2;
        const float u2y = a2.y * (1.0f - f2) + b2v.y * f2;
        const float fx = w0 * v0.x + w1 * u1x + w2 * u2x;
        const float fy = w0 * v0.y + w1 * u1y + w2 * u2y;
        *(__half2*)(fused_pre_h + (size_t)r * DINNER + c) = __floats2half2_rn(fx, fy);
        *(__half2*)(ctx_h + (size_t)r * DINNER + c) =
            __floats2half2_rn((v0.x + u1x + u2x) * (1.0f / 3.0f),
                              (v0.y + u1y + u2y) * (1.0f / 3.0f));
    }
}

// ---------------------------------------------------------------------------
// In-place LayerNorm over last dim (1024)
// ---------------------------------------------------------------------------
__global__ void ln_kernel(float* __restrict__ y,
                          const float* __restrict__ g, const float* __restrict__ b)
{
    const int r = blockIdx.x;
    const size_t base = (size_t)r * DIM;
    float v[4];
    float s = 0.0f;
#pragma unroll
    for (int i = 0; i < 4; i++) {
        v[i] = y[base + threadIdx.x + i * 256];
        s += v[i];
    }
    __shared__ float red[8];
    __shared__ float mu_sh, rs_sh;
    for (int o = 16; o; o >>= 1) s += __shfl_xor_sync(0xffffffffu, s, o);
    if ((threadIdx.x & 31) == 0) red[threadIdx.x >> 5] = s;
    __syncthreads();
    if (threadIdx.x == 0) {
        float t = 0.0f;
        for (int i = 0; i < 8; i++) t += red[i];
        mu_sh = t / (float)DIM;
    }
    __syncthreads();
    const float mu = mu_sh;
    float q = 0.0f;
#pragma unroll
    for (int i = 0; i < 4; i++) { const float d = v[i] - mu; q += d * d; }
    __syncthreads();
    for (int o = 16; o; o >>= 1) q += __shfl_xor_sync(0xffffffffu, q, o);
    if ((threadIdx.x & 31) == 0) red[threadIdx.x >> 5] = q;
    __syncthreads();
    if (threadIdx.x == 0) {
        float t = 0.0f;
        for (int i = 0; i < 8; i++) t += red[i];
        rs_sh = rsqrtf(t / (float)DIM + 1e-5f);
    }
    __syncthreads();
    const float rs = rs_sh;
#pragma unroll
    for (int i = 0; i < 4; i++) {
        const int c = threadIdx.x + i * 256;
        y[base + c] = (v[i] - mu) * rs * g[c] + b[c];
    }
}

// ---------------------------------------------------------------------------
// Launcher
// ---------------------------------------------------------------------------
extern "C" void kernel_launch(void* const* d_in, const int* in_sizes, int n_in,
                              void* d_out, int out_size)
{
    const float* x         = (const float*)d_in[0];
    const float* in_proj_w = (const float*)d_in[1];
    const float* conv_w    = (const float*)d_in[2];
    const float* conv_b    = (const float*)d_in[3];
    const float* xproj_w   = (const float*)d_in[4];
    const float* dtproj_w  = (const float*)d_in[5];
    const float* dtproj_b  = (const float*)d_in[6];
    const float* D_param   = (const float*)d_in[7];
    const float* sw        = (const float*)d_in[8];
    const float* cg_w1     = (const float*)d_in[9];
    const float* cg_w2     = (const float*)d_in[10];
    const float* out_proj  = (const float*)d_in[11];
    const float* ln_g      = (const float*)d_in[12];
    const float* ln_b      = (const float*)d_in[13];
    float* out = (float*)d_out;

    float  *xin, *xs1, *xs2, *y0, *y1, *y2;
    __half *gate_h, *x_h, *ctx_h, *h_h, *fused_h, *fusedpre_h, *wTh;
    cudaGetSymbolAddress((void**)&xin,        g_xin);
    cudaGetSymbolAddress((void**)&gate_h,     g_gate_h);
    cudaGetSymbolAddress((void**)&xs1,        g_xs1);
    cudaGetSymbolAddress((void**)&xs2,        g_xs2);
    cudaGetSymbolAddress((void**)&y0,         g_y0);
    cudaGetSymbolAddress((void**)&y1,         g_y1);
    cudaGetSymbolAddress((void**)&y2,         g_y2);
    cudaGetSymbolAddress((void**)&x_h,        g_x_h);
    cudaGetSymbolAddress((void**)&ctx_h,      g_ctx_h);
    cudaGetSymbolAddress((void**)&h_h,        g_h_h);
    cudaGetSymbolAddress((void**)&fused_h,    g_fused_h);
    cudaGetSymbolAddress((void**)&fusedpre_h, g_fusedpre_h);
    cudaGetSymbolAddress((void**)&wTh,        g_wTh);

    __half* wt_in  = wTh;
    __half* wt_cg1 = wt_in  + (size_t)DIM * 2 * DINNER;
    __half* wt_cg2 = wt_cg1 + (size_t)DINNER * (DINNER/2);
    __half* wt_out = wt_cg2 + (size_t)(DINNER/2) * DINNER;

    cudaFuncSetAttribute(tgemm_kernel<1>, cudaFuncAttributeMaxDynamicSharedMemorySize, SM_TOTAL2);
    cudaFuncSetAttribute(tgemm_kernel<2>, cudaFuncAttributeMaxDynamicSharedMemorySize, SM_TOTAL2);
    cudaFuncSetAttribute(tgemm_kernel<3>, cudaFuncAttributeMaxDynamicSharedMemorySize, SM_TOTAL2);
    cudaFuncSetAttribute(tgemm_kernel<4>, cudaFuncAttributeMaxDynamicSharedMemorySize, SM_TOTAL2);
    cudaFuncSetAttribute(ssm2_kernel,     cudaFuncAttributeMaxDynamicSharedMemorySize, SSM_SMEM);

    // 0) prepare half operands
    f2h_kernel<<<(MTOK * DIM / 4 + 255) / 256, 256>>>(x, x_h, MTOK * DIM / 4);
    transpose_kernel<<<dim3((2*DINNER)/32, DIM/32),    dim3(32, 8)>>>(in_proj_w, wt_in,  DIM,      2*DINNER);
    transpose_kernel<<<dim3((DINNER/2)/32, DINNER/32), dim3(32, 8)>>>(cg_w1,     wt_cg1, DINNER,   DINNER/2);
    transpose_kernel<<<dim3(DINNER/32, (DINNER/2)/32), dim3(32, 8)>>>(cg_w2,     wt_cg2, DINNER/2, DINNER);
    transpose_kernel<<<dim3(DIM/32, DINNER/32),        dim3(32, 8)>>>(out_proj,  wt_out, DINNER,   DIM);

    // 1) [x_in | silu(gate)] = x @ in_proj_w
    tgemm_kernel<4><<<dim3((2*DINNER)/BNT, MTOK/BMT), 256, SM_TOTAL2>>>(
        x_h, wt_in, xin, MTOK, 2*DINNER, DIM, nullptr, nullptr, gate_h);

    // 2) downsample x_in
    down_kernel<<<MTOK / 2, 256>>>(xin, xs1, 2, TLEN / 2);
    down_kernel<<<MTOK / 4, 256>>>(xin, xs2, 4, TLEN / 4);

    // 3) per-scale fused SSM core
    ssm2_kernel<<<MTOK / SSM_R, 256, SSM_SMEM>>>(xin,
                              conv_w + 0 * DINNER * KCONV, conv_b + 0 * DINNER,
                              xproj_w + 0 * DINNER * 2 * DSTATE,
                              dtproj_w + 0 * DSTATE * DINNER,
                              dtproj_b + 0 * DINNER, D_param + 0 * DINNER,
                              y0, TLEN);
    ssm2_kernel<<<(MTOK/2) / SSM_R, 256, SSM_SMEM>>>(xs1,
                              conv_w + 1 * DINNER * KCONV, conv_b + 1 * DINNER,
                              xproj_w + 1 * DINNER * 2 * DSTATE,
                              dtproj_w + 1 * DSTATE * DINNER,
                              dtproj_b + 1 * DINNER, D_param + 1 * DINNER,
                              y1, TLEN / 2);
    ssm2_kernel<<<(MTOK/4) / SSM_R, 256, SSM_SMEM>>>(xs2,
                              conv_w + 2 * DINNER * KCONV, conv_b + 2 * DINNER,
                              xproj_w + 2 * DINNER * 2 * DSTATE,
                              dtproj_w + 2 * DSTATE * DINNER,
                              dtproj_b + 2 * DINNER, D_param + 2 * DINNER,
                              y2, TLEN / 4);

    // 4) upsample + fuse (half) + ctx (half)
    mix_kernel<<<MTOK, 256>>>(y0, y1, y2, sw, fusedpre_h, ctx_h);

    // 5) h = silu(ctx @ cg_w1) -> half
    tgemm_kernel<1><<<dim3((DINNER/2)/BNT, MTOK/BMT), 256, SM_TOTAL2>>>(
        ctx_h, wt_cg1, h_h, MTOK, DINNER/2, DINNER, nullptr, nullptr, nullptr);

    // 6) fused_h = fused_pre * sigmoid(h @ cg_w2) * silu_gate
    tgemm_kernel<2><<<dim3(DINNER/BNT, MTOK/BMT), 256, SM_TOTAL2>>>(
        h_h, wt_cg2, fused_h, MTOK, DINNER, DINNER/2, nullptr, fusedpre_h, gate_h);

    // 7) out = fused_h @ out_proj + residual
    tgemm_kernel<3><<<dim3(DIM/BNT, MTOK/BMT), 256, SM_TOTAL2>>>(
        fused_h, wt_out, out, MTOK, DIM, DINNER, x, nullptr, nullptr);

    // 8) in-place LayerNorm
    ln_kernel<<<MTOK, 256>>>(out, ln_g, ln_b);
}

// round 12
// speedup vs baseline: 1.0499x; 1.0499x over previous
#include <cuda_runtime.h>
#include <cuda_fp16.h>
#include <math.h>
#include <stdint.h>

// ---------------------------------------------------------------------------
// Problem constants
// ---------------------------------------------------------------------------
#define BATCH     4
#define TLEN      4096
#define MTOK      (BATCH * TLEN)      // 16384 tokens
#define DIM       1024
#define DINNER    2048
#define DSTATE    16
#define KCONV     4
#define SSM_R     32

// ---------------------------------------------------------------------------
// Scratch buffers (static device globals; no allocation anywhere)
// ---------------------------------------------------------------------------
__device__ float  g_xin  [(size_t)MTOK * DINNER];
__device__ __half g_gate_h[(size_t)MTOK * DINNER];
__device__ float  g_xs1  [(size_t)(MTOK/2) * DINNER];
__device__ float  g_xs2  [(size_t)(MTOK/4) * DINNER];
__device__ float  g_y0   [(size_t)MTOK     * DINNER];
__device__ float  g_y1   [(size_t)(MTOK/2) * DINNER];
__device__ float  g_y2   [(size_t)(MTOK/4) * DINNER];
__device__ __half g_fusedpre_h[(size_t)MTOK * DINNER];
__device__ __half g_x_h    [(size_t)MTOK * DIM];
__device__ __half g_ctx_h  [(size_t)MTOK * DINNER];
__device__ __half g_h_h    [(size_t)MTOK * (DINNER/2)];
__device__ __half g_fused_h[(size_t)MTOK * DINNER];
__device__ __half g_wTh  [(size_t)(DIM*2*DINNER) + (size_t)(DINNER*(DINNER/2))
                          + (size_t)((DINNER/2)*DINNER) + (size_t)(DINNER*DIM)];

// ---------------------------------------------------------------------------
// Math helpers
// ---------------------------------------------------------------------------
__device__ __forceinline__ float sigmoidf_(float x) { return 1.0f / (1.0f + expf(-x)); }
__device__ __forceinline__ float siluf_(float x)    { return x / (1.0f + expf(-x)); }
__device__ __forceinline__ float softplusf_(float x) {
    return x > 0.0f ? x + log1pf(expf(-x)) : log1pf(expf(x));
}

// ---------------------------------------------------------------------------
// PTX helpers
// ---------------------------------------------------------------------------
__device__ __forceinline__ uint32_t smem_u32(const void* p) {
    uint32_t a;
    asm("{ .reg .u64 t; cvta.to.shared.u64 t, %1; cvt.u32.u64 %0, t; }" : "=r"(a) : "l"(p));
    return a;
}
__device__ __forceinline__ void cp_async16(uint32_t saddr, const void* gaddr) {
    asm volatile("cp.async.cg.shared.global [%0], [%1], 16;"
                 :: "r"(saddr), "l"(gaddr) : "memory");
}
#define CP_COMMIT() asm volatile("cp.async.commit_group;" ::: "memory")
#define CP_WAIT(n)  asm volatile("cp.async.wait_group %0;" :: "n"(n) : "memory")

__device__ __forceinline__ void ldsm_x4(uint32_t* r, uint32_t addr) {
    asm volatile("ldmatrix.sync.aligned.m8n8.x4.shared.b16 {%0,%1,%2,%3}, [%4];"
                 : "=r"(r[0]), "=r"(r[1]), "=r"(r[2]), "=r"(r[3]) : "r"(addr));
}
__device__ __forceinline__ void mma_f16(float* d, const uint32_t* a, const uint32_t* b) {
    asm volatile(
        "mma.sync.aligned.m16n8k16.row.col.f32.f16.f16.f32 "
        "{%0,%1,%2,%3}, {%4,%5,%6,%7}, {%8,%9}, {%0,%1,%2,%3};"
        : "+f"(d[0]), "+f"(d[1]), "+f"(d[2]), "+f"(d[3])
        : "r"(a[0]), "r"(a[1]), "r"(a[2]), "r"(a[3]), "r"(b[0]), "r"(b[1]));
}

// ---------------------------------------------------------------------------
// FP16 tensor-core GEMM v3: C[M,N] = A[M,K] @ Bt[N,K]^T, fp32 accumulate.
// Block tile 128x128, 4 warps (2x2), warp tile 64x64, 2 CTAs/SM.
// 3-stage cp.async. Per k16 step: 8 ldmatrix.x4 feed 32 MMAs.
// EPI: 1 silu->half, 2 cg-combine->half, 3 +residual->f32,
//      4 split x_in f32 | silu(gate) half
// ---------------------------------------------------------------------------
#define STAGES      3
#define TILE_BYTESH 16384                     // 128 rows * 128B
#define SM_TOTALH   (STAGES * 2 * TILE_BYTESH)   // 98304

template <int EPI>
__global__ __launch_bounds__(128, 2)
void tgemm_kernel(const __half* __restrict__ A, const __half* __restrict__ Bt,
                  void* __restrict__ Cv, int M, int N, int K,
                  const float* __restrict__ aux, const __half* __restrict__ aux2h,
                  __half* __restrict__ auxh)
{
    extern __shared__ char smem[];
    const uint32_t sbase = smem_u32(smem);
    const int tid = threadIdx.x;
    const int lid = tid & 31;
    const int wid = tid >> 5;         // 0..3
    const int warp_m = wid & 1;       // 2 x 64 rows
    const int warp_n = wid >> 1;      // 2 x 64 cols
    const int bn = blockIdx.x, bm = blockIdx.y;

    const __half* Abase = A  + (size_t)bm * 128 * K;
    const __half* Bbase = Bt + (size_t)bn * 128 * K;
    const int nk = K >> 6;

    auto issue_copy = [&](int chunk, int buf) {
        const int k0 = chunk << 6;
        const int u  = tid & 7;
        const uint32_t sa = sbase + buf * (2 * TILE_BYTESH);
        const uint32_t sb = sa + TILE_BYTESH;
#pragma unroll
        for (int i = 0; i < 8; i++) {
            const int r = (tid >> 3) + i * 16;
            const uint32_t so = (uint32_t)(r * 128 + ((u ^ (r & 7)) << 4));
            cp_async16(sa + so, Abase + (size_t)r * K + k0 + u * 8);
            cp_async16(sb + so, Bbase + (size_t)r * K + k0 + u * 8);
        }
        CP_COMMIT();
    };

    float acc[4][8][4];
#pragma unroll
    for (int i = 0; i < 4; i++)
#pragma unroll
        for (int j = 0; j < 8; j++)
#pragma unroll
            for (int c = 0; c < 4; c++) acc[i][j][c] = 0.0f;

    issue_copy(0, 0);
    if (nk > 1) issue_copy(1, 1);

    for (int it = 0; it < nk; ++it) {
        if (it + 2 < nk) { issue_copy(it + 2, (it + 2) % STAGES); CP_WAIT(2); }
        else if (it + 1 < nk) { CP_WAIT(1); }
        else { CP_WAIT(0); }
        __syncthreads();

        const uint32_t a_s = sbase + (it % STAGES) * (2 * TILE_BYTESH);
        const uint32_t b_s = a_s + TILE_BYTESH;

#pragma unroll
        for (int ks = 0; ks < 4; ks++) {
            const int ub = ks * 2;
            uint32_t af[4][4];
#pragma unroll
            for (int mf = 0; mf < 4; mf++) {
                const int row  = warp_m * 64 + mf * 16 + (lid & 15);
                const int unit = ub + (lid >> 4);
                ldsm_x4(af[mf], a_s + (uint32_t)(row * 128 + ((unit ^ (row & 7)) << 4)));
            }
            uint32_t bf[8][2];
#pragma unroll
            for (int p = 0; p < 4; p++) {
                const int row  = warp_n * 64 + p * 16 + ((lid >> 4) & 1) * 8 + (lid & 7);
                const int unit = ub + ((lid >> 3) & 1);
                uint32_t t[4];
                ldsm_x4(t, b_s + (uint32_t)(row * 128 + ((unit ^ (row & 7)) << 4)));
                bf[p * 2][0] = t[0]; bf[p * 2][1] = t[1];
                bf[p * 2 + 1][0] = t[2]; bf[p * 2 + 1][1] = t[3];
            }
#pragma unroll
            for (int mf = 0; mf < 4; mf++)
#pragma unroll
                for (int nf = 0; nf < 8; nf++)
                    mma_f16(acc[mf][nf], af[mf], bf[nf]);
        }
        __syncthreads();
    }

    // Epilogue
#pragma unroll
    for (int mf = 0; mf < 4; mf++)
#pragma unroll
        for (int nf = 0; nf < 8; nf++)
#pragma unroll
            for (int hh = 0; hh < 2; hh++) {
                const int row = bm * 128 + warp_m * 64 + mf * 16 + (lid >> 2) + hh * 8;
                const int col = bn * 128 + warp_n * 64 + nf * 8 + (lid & 3) * 2;
                float2 v = make_float2(acc[mf][nf][hh * 2], acc[mf][nf][hh * 2 + 1]);
                const size_t idx = (size_t)row * N + col;
                if (EPI == 1) {
                    *(__half2*)((__half*)Cv + idx) =
                        __floats2half2_rn(siluf_(v.x), siluf_(v.y));
                } else if (EPI == 2) {
                    const float2 f  = __half22float2(*(const __half2*)(aux2h + idx));
                    const float2 gt = __half22float2(*(const __half2*)(auxh + idx));
                    const float ox = f.x * sigmoidf_(v.x) * gt.x;
                    const float oy = f.y * sigmoidf_(v.y) * gt.y;
                    *(__half2*)((__half*)Cv + idx) = __floats2half2_rn(ox, oy);
                } else if (EPI == 3) {
                    const float2 rr = *(const float2*)(aux + idx);
                    v.x += rr.x; v.y += rr.y;
                    *(float2*)((float*)Cv + idx) = v;
                } else { // EPI == 4
                    if (col < DINNER) {
                        *(float2*)((float*)Cv + (size_t)row * DINNER + col) = v;
                    } else {
                        *(__half2*)(auxh + (size_t)row * DINNER + (col - DINNER)) =
                            __floats2half2_rn(siluf_(v.x), siluf_(v.y));
                    }
                }
            }
}

// ---------------------------------------------------------------------------
// fp32 -> fp16 convert
// ---------------------------------------------------------------------------
__global__ void f2h_kernel(const float* __restrict__ in, __half* __restrict__ out,
                           int n4)
{
    const int i = blockIdx.x * 256 + threadIdx.x;
    if (i < n4) {
        const float4 v = *(const float4*)(in + (size_t)i * 4);
        ((__half2*)out)[(size_t)i * 2]     = __floats2half2_rn(v.x, v.y);
        ((__half2*)out)[(size_t)i * 2 + 1] = __floats2half2_rn(v.z, v.w);
    }
}

// ---------------------------------------------------------------------------
// Weight transpose: in[K,N] fp32 -> out[N,K] fp16
// ---------------------------------------------------------------------------
__global__ void transpose_kernel(const float* __restrict__ in, __half* __restrict__ out,
                                 int K, int N)
{
    __shared__ float t[32][33];
    const int n0 = blockIdx.x * 32, k0 = blockIdx.y * 32;
    const int tx = threadIdx.x, ty = threadIdx.y;
#pragma unroll
    for (int i = 0; i < 32; i += 8)
        t[ty + i][tx] = in[(size_t)(k0 + ty + i) * N + n0 + tx];
    __syncthreads();
#pragma unroll
    for (int i = 0; i < 32; i += 8)
        out[(size_t)(n0 + ty + i) * K + k0 + tx] = __float2half(t[tx][ty + i]);
}

// ---------------------------------------------------------------------------
// Downsample (mean pooling over time, factor 2 or 4) from x_in
// ---------------------------------------------------------------------------
__global__ void down_kernel(const float* __restrict__ xin, float* __restrict__ out,
                            int factor, int Tout)
{
    const int r = blockIdx.x;
    const int b = r / Tout, t = r % Tout;
    const float inv = 1.0f / (float)factor;
    const size_t srow = ((size_t)b * TLEN + (size_t)t * factor) * DINNER;
    for (int c4 = threadIdx.x; c4 < DINNER / 4; c4 += 256) {
        const int c = c4 * 4;
        float4 s = make_float4(0.f, 0.f, 0.f, 0.f);
        for (int k = 0; k < factor; k++) {
            const float4 v = *(const float4*)(xin + srow + (size_t)k * DINNER + c);
            s.x += v.x; s.y += v.y; s.z += v.z; s.w += v.w;
        }
        s.x *= inv; s.y *= inv; s.z *= inv; s.w *= inv;
        *(float4*)(out + (size_t)r * DINNER + c) = s;
    }
}

// ---------------------------------------------------------------------------
// Fused SSM core v2 (unchanged from R7 win)
// ---------------------------------------------------------------------------
#define SSM_SMEM (DINNER * DSTATE * 2 * 2)   // 131072

__global__ __launch_bounds__(256)
void ssm2_kernel(const float* __restrict__ X,
                 const float* __restrict__ cw,
                 const float* __restrict__ cb,
                 const float* __restrict__ xw,
                 const float* __restrict__ dtw,
                 const float* __restrict__ dtb,
                 const float* __restrict__ Dp,
                 float* __restrict__ y, int Ts)
{
    extern __shared__ __half sh[];
    __half* s_xw  = sh;
    __half* s_dtw = sh + DINNER * DSTATE;
    __shared__ float s_wp[8][16];
    __shared__ float s_B[DSTATE];

    const int tid = threadIdx.x;
    const int lane = tid & 31, warp = tid >> 5;
    const int c0 = tid * 8;
    const int r0 = blockIdx.x * SSM_R;
    const int trow0 = r0 % Ts;

    for (int idx = tid; idx < DINNER * DSTATE; idx += 256) {
        const int c = idx >> 4, j = idx & 15;
        s_xw[idx] = __float2half(xw[c * (2 * DSTATE) + j]);
    }
    for (int idx = tid; idx < DSTATE * DINNER; idx += 256)
        s_dtw[idx] = __float2half(dtw[idx]);

    float4 cw4[8];
#pragma unroll
    for (int i = 0; i < 8; i++) cw4[i] = *(const float4*)(cw + (size_t)(c0 + i) * 4);
    float cbv[8], dtbv[8], Dv[8];
    {
        const float4 a = *(const float4*)(cb + c0);
        const float4 b = *(const float4*)(cb + c0 + 4);
        cbv[0]=a.x; cbv[1]=a.y; cbv[2]=a.z; cbv[3]=a.w;
        cbv[4]=b.x; cbv[5]=b.y; cbv[6]=b.z; cbv[7]=b.w;
        const float4 c1 = *(const float4*)(dtb + c0);
        const float4 c2 = *(const float4*)(dtb + c0 + 4);
        dtbv[0]=c1.x; dtbv[1]=c1.y; dtbv[2]=c1.z; dtbv[3]=c1.w;
        dtbv[4]=c2.x; dtbv[5]=c2.y; dtbv[6]=c2.z; dtbv[7]=c2.w;
        const float4 d1 = *(const float4*)(Dp + c0);
        const float4 d2 = *(const float4*)(Dp + c0 + 4);
        Dv[0]=d1.x; Dv[1]=d1.y; Dv[2]=d1.z; Dv[3]=d1.w;
        Dv[4]=d2.x; Dv[5]=d2.y; Dv[6]=d2.z; Dv[7]=d2.w;
    }

    auto loadrow = [&](int row, float* v) {
        const float4 a = *(const float4*)(X + (size_t)row * DINNER + c0);
        const float4 b = *(const float4*)(X + (size_t)row * DINNER + c0 + 4);
        v[0]=a.x; v[1]=a.y; v[2]=a.z; v[3]=a.w;
        v[4]=b.x; v[5]=b.y; v[6]=b.z; v[7]=b.w;
    };

    float w0[8], w1[8], w2[8], cur[8];
    if (trow0 == 0) {
#pragma unroll
        for (int i = 0; i < 8; i++) { w0[i] = 0.f; w1[i] = 0.f; w2[i] = 0.f; }
    } else {
        loadrow(r0 - 3, w0);
        loadrow(r0 - 2, w1);
        loadrow(r0 - 1, w2);
    }
    __syncthreads();

    for (int r = 0; r < SSM_R; r++) {
        const int row = r0 + r;
        loadrow(row, cur);

        float xc[8];
#pragma unroll
        for (int i = 0; i < 8; i++) {
            const float a = cbv[i] + cw4[i].x * w0[i] + cw4[i].y * w1[i]
                          + cw4[i].z * w2[i] + cw4[i].w * cur[i];
            xc[i] = siluf_(a);
        }

        float part[16];
#pragma unroll
        for (int j = 0; j < 16; j++) part[j] = 0.0f;
#pragma unroll
        for (int i = 0; i < 8; i++) {
            const __half2* p = (const __half2*)&s_xw[(c0 + i) * 16];
            const float xi = xc[i];
#pragma unroll
            for (int j2 = 0; j2 < 8; j2++) {
                const float2 f = __half22float2(p[j2]);
                part[j2 * 2]     += xi * f.x;
                part[j2 * 2 + 1] += xi * f.y;
            }
        }
#pragma unroll
        for (int j = 0; j < 16; j++)
#pragma unroll
            for (int o = 16; o; o >>= 1)
                part[j] += __shfl_xor_sync(0xffffffffu, part[j], o);
        if (lane == 0) {
#pragma unroll
            for (int j = 0; j < 16; j++) s_wp[warp][j] = part[j];
        }
        __syncthreads();
        if (tid < 16) {
            float s = 0.0f;
#pragma unroll
            for (int w = 0; w < 8; w++) s += s_wp[w][tid];
            s_B[tid] = s;
        }
        __syncthreads();

        float lo[8];
#pragma unroll
        for (int i = 0; i < 8; i++) lo[i] = dtbv[i];
#pragma unroll
        for (int j = 0; j < DSTATE; j++) {
            const float bj = s_B[j];
            const __half2* p = (const __half2*)&s_dtw[j * DINNER + c0];
#pragma unroll
            for (int i2 = 0; i2 < 4; i2++) {
                const float2 f = __half22float2(p[i2]);
                lo[i2 * 2]     += bj * f.x;
                lo[i2 * 2 + 1] += bj * f.y;
            }
        }
        float yv[8];
#pragma unroll
        for (int i = 0; i < 8; i++)
            yv[i] = xc[i] * sigmoidf_(softplusf_(lo[i])) + Dv[i] * cur[i];
        *(float4*)(y + (size_t)row * DINNER + c0)     = make_float4(yv[0], yv[1], yv[2], yv[3]);
        *(float4*)(y + (size_t)row * DINNER + c0 + 4) = make_float4(yv[4], yv[5], yv[6], yv[7]);

#pragma unroll
        for (int i = 0; i < 8; i++) { w0[i] = w1[i]; w1[i] = w2[i]; w2[i] = cur[i]; }
        __syncthreads();
    }
}

// ---------------------------------------------------------------------------
// Linear upsample + softmax-weighted mix + ctx (both half)
// ---------------------------------------------------------------------------
__global__ void mix_kernel(const float* __restrict__ y0,
                           const float* __restrict__ y1,
                           const float* __restrict__ y2,
                           const float* __restrict__ sw,
                           __half* __restrict__ fused_pre_h,
                           __half* __restrict__ ctx_h)
{
    const int r = blockIdx.x;
    const int b = r >> 12, t = r & (TLEN - 1);

    const float s0 = sw[0], s1 = sw[1], s2 = sw[2];
    const float m  = fmaxf(s0, fmaxf(s1, s2));
    const float e0 = expf(s0 - m), e1 = expf(s1 - m), e2 = expf(s2 - m);
    const float inv = 1.0f / (e0 + e1 + e2);
    const float w0 = e0 * inv, w1 = e1 * inv, w2 = e2 * inv;

    float c1 = fminf(fmaxf((t + 0.5f) * 0.5f - 0.5f, 0.0f), (float)(TLEN / 2 - 1));
    int lo1 = (int)floorf(c1);
    int hi1 = min(lo1 + 1, TLEN / 2 - 1);
    float f1 = c1 - (float)lo1;

    float c2 = fminf(fmaxf((t + 0.5f) * 0.25f - 0.5f, 0.0f), (float)(TLEN / 4 - 1));
    int lo2 = (int)floorf(c2);
    int hi2 = min(lo2 + 1, TLEN / 4 - 1);
    float f2 = c2 - (float)lo2;

    const float* p0  = y0 + (size_t)r * DINNER;
    const float* p1a = y1 + ((size_t)(b * (TLEN / 2) + lo1)) * DINNER;
    const float* p1b = y1 + ((size_t)(b * (TLEN / 2) + hi1)) * DINNER;
    const float* p2a = y2 + ((size_t)(b * (TLEN / 4) + lo2)) * DINNER;
    const float* p2b = y2 + ((size_t)(b * (TLEN / 4) + hi2)) * DINNER;

    for (int c = threadIdx.x * 2; c < DINNER; c += 512) {
        const float2 v0  = *(const float2*)(p0 + c);
        const float2 a1  = *(const float2*)(p1a + c);
        const float2 b1v = *(const float2*)(p1b + c);
        const float2 a2  = *(const float2*)(p2a + c);
        const float2 b2v = *(const float2*)(p2b + c);
        const float u1x = a1.x * (1.0f - f1) + b1v.x * f1;
        const float u1y = a1.y * (1.0f - f1) + b1v.y * f1;
        const float u2x = a2.x * (1.0f - f2) + b2v.x * f2;
        const float u2y = a2.y * (1.0f - f2) + b2v.y * f2;
        const float fx = w0 * v0.x + w1 * u1x + w2 * u2x;
        const float fy = w0 * v0.y + w1 * u1y + w2 * u2y;
        *(__half2*)(fused_pre_h + (size_t)r * DINNER + c) = __floats2half2_rn(fx, fy);
        *(__half2*)(ctx_h + (size_t)r * DINNER + c) =
            __floats2half2_rn((v0.x + u1x + u2x) * (1.0f / 3.0f),
                              (v0.y + u1y + u2y) * (1.0f / 3.0f));
    }
}

// ---------------------------------------------------------------------------
// In-place LayerNorm over last dim (1024)
// ---------------------------------------------------------------------------
__global__ void ln_kernel(float* __restrict__ y,
                          const float* __restrict__ g, const float* __restrict__ b)
{
    const int r = blockIdx.x;
    const size_t base = (size_t)r * DIM;
    float v[4];
    float s = 0.0f;
#pragma unroll
    for (int i = 0; i < 4; i++) {
        v[i] = y[base + threadIdx.x + i * 256];
        s += v[i];
    }
    __shared__ float red[8];
    __shared__ float mu_sh, rs_sh;
    for (int o = 16; o; o >>= 1) s += __shfl_xor_sync(0xffffffffu, s, o);
    if ((threadIdx.x & 31) == 0) red[threadIdx.x >> 5] = s;
    __syncthreads();
    if (threadIdx.x == 0) {
        float t = 0.0f;
        for (int i = 0; i < 8; i++) t += red[i];
        mu_sh = t / (float)DIM;
    }
    __syncthreads();
    const float mu = mu_sh;
    float q = 0.0f;
#pragma unroll
    for (int i = 0; i < 4; i++) { const float d = v[i] - mu; q += d * d; }
    __syncthreads();
    for (int o = 16; o; o >>= 1) q += __shfl_xor_sync(0xffffffffu, q, o);
    if ((threadIdx.x & 31) == 0) red[threadIdx.x >> 5] = q;
    __syncthreads();
    if (threadIdx.x == 0) {
        float t = 0.0f;
        for (int i = 0; i < 8; i++) t += red[i];
        rs_sh = rsqrtf(t / (float)DIM + 1e-5f);
    }
    __syncthreads();
    const float rs = rs_sh;
#pragma unroll
    for (int i = 0; i < 4; i++) {
        const int c = threadIdx.x + i * 256;
        y[base + c] = (v[i] - mu) * rs * g[c] + b[c];
    }
}

// ---------------------------------------------------------------------------
// Launcher
// ---------------------------------------------------------------------------
extern "C" void kernel_launch(void* const* d_in, const int* in_sizes, int n_in,
                              void* d_out, int out_size)
{
    const float* x         = (const float*)d_in[0];
    const float* in_proj_w = (const float*)d_in[1];
    const float* conv_w    = (const float*)d_in[2];
    const float* conv_b    = (const float*)d_in[3];
    const float* xproj_w   = (const float*)d_in[4];
    const float* dtproj_w  = (const float*)d_in[5];
    const float* dtproj_b  = (const float*)d_in[6];
    const float* D_param   = (const float*)d_in[7];
    const float* sw        = (const float*)d_in[8];
    const float* cg_w1     = (const float*)d_in[9];
    const float* cg_w2     = (const float*)d_in[10];
    const float* out_proj  = (const float*)d_in[11];
    const float* ln_g      = (const float*)d_in[12];
    const float* ln_b      = (const float*)d_in[13];
    float* out = (float*)d_out;

    float  *xin, *xs1, *xs2, *y0, *y1, *y2;
    __half *gate_h, *x_h, *ctx_h, *h_h, *fused_h, *fusedpre_h, *wTh;
    cudaGetSymbolAddress((void**)&xin,        g_xin);
    cudaGetSymbolAddress((void**)&gate_h,     g_gate_h);
    cudaGetSymbolAddress((void**)&xs1,        g_xs1);
    cudaGetSymbolAddress((void**)&xs2,        g_xs2);
    cudaGetSymbolAddress((void**)&y0,         g_y0);
    cudaGetSymbolAddress((void**)&y1,         g_y1);
    cudaGetSymbolAddress((void**)&y2,         g_y2);
    cudaGetSymbolAddress((void**)&x_h,        g_x_h);
    cudaGetSymbolAddress((void**)&ctx_h,      g_ctx_h);
    cudaGetSymbolAddress((void**)&h_h,        g_h_h);
    cudaGetSymbolAddress((void**)&fused_h,    g_fused_h);
    cudaGetSymbolAddress((void**)&fusedpre_h, g_fusedpre_h);
    cudaGetSymbolAddress((void**)&wTh,        g_wTh);

    __half* wt_in  = wTh;
    __half* wt_cg1 = wt_in  + (size_t)DIM * 2 * DINNER;
    __half* wt_cg2 = wt_cg1 + (size_t)DINNER * (DINNER/2);
    __half* wt_out = wt_cg2 + (size_t)(DINNER/2) * DINNER;

    cudaFuncSetAttribute(tgemm_kernel<1>, cudaFuncAttributeMaxDynamicSharedMemorySize, SM_TOTALH);
    cudaFuncSetAttribute(tgemm_kernel<2>, cudaFuncAttributeMaxDynamicSharedMemorySize, SM_TOTALH);
    cudaFuncSetAttribute(tgemm_kernel<3>, cudaFuncAttributeMaxDynamicSharedMemorySize, SM_TOTALH);
    cudaFuncSetAttribute(tgemm_kernel<4>, cudaFuncAttributeMaxDynamicSharedMemorySize, SM_TOTALH);
    cudaFuncSetAttribute(ssm2_kernel,     cudaFuncAttributeMaxDynamicSharedMemorySize, SSM_SMEM);

    // 0) prepare half operands
    f2h_kernel<<<(MTOK * DIM / 4 + 255) / 256, 256>>>(x, x_h, MTOK * DIM / 4);
    transpose_kernel<<<dim3((2*DINNER)/32, DIM/32),    dim3(32, 8)>>>(in_proj_w, wt_in,  DIM,      2*DINNER);
    transpose_kernel<<<dim3((DINNER/2)/32, DINNER/32), dim3(32, 8)>>>(cg_w1,     wt_cg1, DINNER,   DINNER/2);
    transpose_kernel<<<dim3(DINNER/32, (DINNER/2)/32), dim3(32, 8)>>>(cg_w2,     wt_cg2, DINNER/2, DINNER);
    transpose_kernel<<<dim3(DIM/32, DINNER/32),        dim3(32, 8)>>>(out_proj,  wt_out, DINNER,   DIM);

    // 1) [x_in | silu(gate)] = x @ in_proj_w
    tgemm_kernel<4><<<dim3((2*DINNER)/128, MTOK/128), 128, SM_TOTALH>>>(
        x_h, wt_in, xin, MTOK, 2*DINNER, DIM, nullptr, nullptr, gate_h);

    // 2) downsample x_in
    down_kernel<<<MTOK / 2, 256>>>(xin, xs1, 2, TLEN / 2);
    down_kernel<<<MTOK / 4, 256>>>(xin, xs2, 4, TLEN / 4);

    // 3) per-scale fused SSM core
    ssm2_kernel<<<MTOK / SSM_R, 256, SSM_SMEM>>>(xin,
                              conv_w + 0 * DINNER * KCONV, conv_b + 0 * DINNER,
                              xproj_w + 0 * DINNER * 2 * DSTATE,
                              dtproj_w + 0 * DSTATE * DINNER,
                              dtproj_b + 0 * DINNER, D_param + 0 * DINNER,
                              y0, TLEN);
    ssm2_kernel<<<(MTOK/2) / SSM_R, 256, SSM_SMEM>>>(xs1,
                              conv_w + 1 * DINNER * KCONV, conv_b + 1 * DINNER,
                              xproj_w + 1 * DINNER * 2 * DSTATE,
                              dtproj_w + 1 * DSTATE * DINNER,
                              dtproj_b + 1 * DINNER, D_param + 1 * DINNER,
                              y1, TLEN / 2);
    ssm2_kernel<<<(MTOK/4) / SSM_R, 256, SSM_SMEM>>>(xs2,
                              conv_w + 2 * DINNER * KCONV, conv_b + 2 * DINNER,
                              xproj_w + 2 * DINNER * 2 * DSTATE,
                              dtproj_w + 2 * DSTATE * DINNER,
                              dtproj_b + 2 * DINNER, D_param + 2 * DINNER,
                              y2, TLEN / 4);

    // 4) upsample + fuse (half) + ctx (half)
    mix_kernel<<<MTOK, 256>>>(y0, y1, y2, sw, fusedpre_h, ctx_h);

    // 5) h = silu(ctx @ cg_w1) -> half
    tgemm_kernel<1><<<dim3((DINNER/2)/128, MTOK/128), 128, SM_TOTALH>>>(
        ctx_h, wt_cg1, h_h, MTOK, DINNER/2, DINNER, nullptr, nullptr, nullptr);

    // 6) fused_h = fused_pre * sigmoid(h @ cg_w2) * silu_gate
    tgemm_kernel<2><<<dim3(DINNER/128, MTOK/128), 128, SM_TOTALH>>>(
        h_h, wt_cg2, fused_h, MTOK, DINNER, DINNER/2, nullptr, fusedpre_h, gate_h);

    // 7) out = fused_h @ out_proj + residual
    tgemm_kernel<3><<<dim3(DIM/128, MTOK/128), 128, SM_TOTALH>>>(
        fused_h, wt_out, out, MTOK, DIM, DINNER, x, nullptr, nullptr);

    // 8) in-place LayerNorm
    ln_kernel<<<MTOK, 256>>>(out, ln_g, ln_b);
}

// round 13
// speedup vs baseline: 1.1387x; 1.0845x over previous
#include <cuda_runtime.h>
#include <cuda_fp16.h>
#include <math.h>
#include <stdint.h>

// ---------------------------------------------------------------------------
// Problem constants
// ---------------------------------------------------------------------------
#define BATCH     4
#define TLEN      4096
#define MTOK      (BATCH * TLEN)      // 16384 tokens
#define DIM       1024
#define DINNER    2048
#define DSTATE    16
#define KCONV     4
#define SSM_R     32

// ---------------------------------------------------------------------------
// Scratch buffers (static device globals; no allocation anywhere)
// ---------------------------------------------------------------------------
__device__ float  g_xin  [(size_t)MTOK * DINNER];
__device__ __half g_gate_h[(size_t)MTOK * DINNER];
__device__ float  g_xs1  [(size_t)(MTOK/2) * DINNER];
__device__ float  g_xs2  [(size_t)(MTOK/4) * DINNER];
__device__ __half g_y0   [(size_t)MTOK     * DINNER];
__device__ __half g_y1   [(size_t)(MTOK/2) * DINNER];
__device__ __half g_y2   [(size_t)(MTOK/4) * DINNER];
__device__ __half g_fusedpre_h[(size_t)MTOK * DINNER];
__device__ __half g_x_h    [(size_t)MTOK * DIM];
__device__ __half g_ctx_h  [(size_t)MTOK * DINNER];
__device__ __half g_h_h    [(size_t)MTOK * (DINNER/2)];
__device__ __half g_fused_h[(size_t)MTOK * DINNER];
__device__ __half g_wTh  [(size_t)(DIM*2*DINNER) + (size_t)(DINNER*(DINNER/2))
                          + (size_t)((DINNER/2)*DINNER) + (size_t)(DINNER*DIM)];

// ---------------------------------------------------------------------------
// Math helpers
// ---------------------------------------------------------------------------
__device__ __forceinline__ float sigmoidf_(float x) { return 1.0f / (1.0f + expf(-x)); }
__device__ __forceinline__ float siluf_(float x)    { return x / (1.0f + expf(-x)); }
__device__ __forceinline__ float softplusf_(float x) {
    return x > 0.0f ? x + log1pf(expf(-x)) : log1pf(expf(x));
}

// ---------------------------------------------------------------------------
// PTX helpers
// ---------------------------------------------------------------------------
__device__ __forceinline__ uint32_t smem_u32(const void* p) {
    uint32_t a;
    asm("{ .reg .u64 t; cvta.to.shared.u64 t, %1; cvt.u32.u64 %0, t; }" : "=r"(a) : "l"(p));
    return a;
}
__device__ __forceinline__ void cp_async16(uint32_t saddr, const void* gaddr) {
    asm volatile("cp.async.cg.shared.global [%0], [%1], 16;"
                 :: "r"(saddr), "l"(gaddr) : "memory");
}
#define CP_COMMIT() asm volatile("cp.async.commit_group;" ::: "memory")
#define CP_WAIT(n)  asm volatile("cp.async.wait_group %0;" :: "n"(n) : "memory")

__device__ __forceinline__ void ldsm_x4(uint32_t* r, uint32_t addr) {
    asm volatile("ldmatrix.sync.aligned.m8n8.x4.shared.b16 {%0,%1,%2,%3}, [%4];"
                 : "=r"(r[0]), "=r"(r[1]), "=r"(r[2]), "=r"(r[3]) : "r"(addr));
}
__device__ __forceinline__ void mma_f16(float* d, const uint32_t* a, const uint32_t* b) {
    asm volatile(
        "mma.sync.aligned.m16n8k16.row.col.f32.f16.f16.f32 "
        "{%0,%1,%2,%3}, {%4,%5,%6,%7}, {%8,%9}, {%0,%1,%2,%3};"
        : "+f"(d[0]), "+f"(d[1]), "+f"(d[2]), "+f"(d[3])
        : "r"(a[0]), "r"(a[1]), "r"(a[2]), "r"(a[3]), "r"(b[0]), "r"(b[1]));
}

// ---------------------------------------------------------------------------
// FP16 tensor-core GEMM (exact R7-win mainloop: 128x128 tile, 8 warps 2x4,
// warp tile 64x32, 2 CTAs/SM, 3-stage cp.async).
// EPI: 1 silu->half, 2 cg-combine->half, 3 +residual->f32,
//      4 split x_in f32 | silu(gate) half
// ---------------------------------------------------------------------------
#define STAGES      3
#define TILE_BYTESH 16384
#define SM_TOTALH   (STAGES * 2 * TILE_BYTESH)   // 98304

template <int EPI>
__global__ __launch_bounds__(256, 2)
void tgemm_kernel(const __half* __restrict__ A, const __half* __restrict__ Bt,
                  void* __restrict__ Cv, int M, int N, int K,
                  const float* __restrict__ aux, const __half* __restrict__ aux2h,
                  __half* __restrict__ auxh)
{
    extern __shared__ char smem[];
    const uint32_t sbase = smem_u32(smem);
    const int tid = threadIdx.x;
    const int lid = tid & 31;
    const int wid = tid >> 5;
    const int warp_m = wid & 1;
    const int warp_n = wid >> 1;
    const int bn = blockIdx.x, bm = blockIdx.y;

    const __half* Abase = A  + (size_t)bm * 128 * K;
    const __half* Bbase = Bt + (size_t)bn * 128 * K;
    const int nk = K >> 6;

    auto issue_copy = [&](int chunk, int buf) {
        const int k0 = chunk << 6;
        const int u  = tid & 7;
        const uint32_t sa = sbase + buf * (2 * TILE_BYTESH);
        const uint32_t sb = sa + TILE_BYTESH;
#pragma unroll
        for (int i = 0; i < 4; i++) {
            const int r = (tid >> 3) + i * 32;
            const uint32_t so = (uint32_t)(r * 128 + ((u ^ (r & 7)) << 4));
            cp_async16(sa + so, Abase + (size_t)r * K + k0 + u * 8);
            cp_async16(sb + so, Bbase + (size_t)r * K + k0 + u * 8);
        }
        CP_COMMIT();
    };

    float acc[4][4][4];
#pragma unroll
    for (int i = 0; i < 4; i++)
#pragma unroll
        for (int j = 0; j < 4; j++)
#pragma unroll
            for (int c = 0; c < 4; c++) acc[i][j][c] = 0.0f;

    issue_copy(0, 0);
    if (nk > 1) issue_copy(1, 1);

    for (int it = 0; it < nk; ++it) {
        if (it + 2 < nk) { issue_copy(it + 2, (it + 2) % STAGES); CP_WAIT(2); }
        else if (it + 1 < nk) { CP_WAIT(1); }
        else { CP_WAIT(0); }
        __syncthreads();

        const uint32_t a_s = sbase + (it % STAGES) * (2 * TILE_BYTESH);
        const uint32_t b_s = a_s + TILE_BYTESH;

#pragma unroll
        for (int ks = 0; ks < 4; ks++) {
            const int ub = ks * 2;
            uint32_t af[4][4];
#pragma unroll
            for (int mf = 0; mf < 4; mf++) {
                const int row  = warp_m * 64 + mf * 16 + (lid & 15);
                const int unit = ub + (lid >> 4);
                ldsm_x4(af[mf], a_s + (uint32_t)(row * 128 + ((unit ^ (row & 7)) << 4)));
            }
            uint32_t bf[4][2];
#pragma unroll
            for (int p = 0; p < 2; p++) {
                const int row  = warp_n * 32 + p * 16 + ((lid >> 4) & 1) * 8 + (lid & 7);
                const int unit = ub + ((lid >> 3) & 1);
                uint32_t t[4];
                ldsm_x4(t, b_s + (uint32_t)(row * 128 + ((unit ^ (row & 7)) << 4)));
                bf[p * 2][0] = t[0]; bf[p * 2][1] = t[1];
                bf[p * 2 + 1][0] = t[2]; bf[p * 2 + 1][1] = t[3];
            }
#pragma unroll
            for (int mf = 0; mf < 4; mf++)
#pragma unroll
                for (int nf = 0; nf < 4; nf++)
                    mma_f16(acc[mf][nf], af[mf], bf[nf]);
        }
        __syncthreads();
    }

    // Epilogue
#pragma unroll
    for (int mf = 0; mf < 4; mf++)
#pragma unroll
        for (int nf = 0; nf < 4; nf++)
#pragma unroll
            for (int hh = 0; hh < 2; hh++) {
                const int row = bm * 128 + warp_m * 64 + mf * 16 + (lid >> 2) + hh * 8;
                const int col = bn * 128 + warp_n * 32 + nf * 8 + (lid & 3) * 2;
                float2 v = make_float2(acc[mf][nf][hh * 2], acc[mf][nf][hh * 2 + 1]);
                const size_t idx = (size_t)row * N + col;
                if (EPI == 1) {
                    *(__half2*)((__half*)Cv + idx) =
                        __floats2half2_rn(siluf_(v.x), siluf_(v.y));
                } else if (EPI == 2) {
                    const float2 f  = __half22float2(*(const __half2*)(aux2h + idx));
                    const float2 gt = __half22float2(*(const __half2*)(auxh + idx));
                    const float ox = f.x * sigmoidf_(v.x) * gt.x;
                    const float oy = f.y * sigmoidf_(v.y) * gt.y;
                    *(__half2*)((__half*)Cv + idx) = __floats2half2_rn(ox, oy);
                } else if (EPI == 3) {
                    const float2 rr = *(const float2*)(aux + idx);
                    v.x += rr.x; v.y += rr.y;
                    *(float2*)((float*)Cv + idx) = v;
                } else { // EPI == 4
                    if (col < DINNER) {
                        *(float2*)((float*)Cv + (size_t)row * DINNER + col) = v;
                    } else {
                        *(__half2*)(auxh + (size_t)row * DINNER + (col - DINNER)) =
                            __floats2half2_rn(siluf_(v.x), siluf_(v.y));
                    }
                }
            }
}

// ---------------------------------------------------------------------------
// fp32 -> fp16 convert
// ---------------------------------------------------------------------------
__global__ void f2h_kernel(const float* __restrict__ in, __half* __restrict__ out,
                           int n4)
{
    const int i = blockIdx.x * 256 + threadIdx.x;
    if (i < n4) {
        const float4 v = *(const float4*)(in + (size_t)i * 4);
        ((__half2*)out)[(size_t)i * 2]     = __floats2half2_rn(v.x, v.y);
        ((__half2*)out)[(size_t)i * 2 + 1] = __floats2half2_rn(v.z, v.w);
    }
}

// ---------------------------------------------------------------------------
// Weight transpose: in[K,N] fp32 -> out[N,K] fp16
// ---------------------------------------------------------------------------
__global__ void transpose_kernel(const float* __restrict__ in, __half* __restrict__ out,
                                 int K, int N)
{
    __shared__ float t[32][33];
    const int n0 = blockIdx.x * 32, k0 = blockIdx.y * 32;
    const int tx = threadIdx.x, ty = threadIdx.y;
#pragma unroll
    for (int i = 0; i < 32; i += 8)
        t[ty + i][tx] = in[(size_t)(k0 + ty + i) * N + n0 + tx];
    __syncthreads();
#pragma unroll
    for (int i = 0; i < 32; i += 8)
        out[(size_t)(n0 + ty + i) * K + k0 + tx] = __float2half(t[tx][ty + i]);
}

// ---------------------------------------------------------------------------
// Fused downsample: read 4 input rows once, emit 2 xs1 rows + 1 xs2 row
// ---------------------------------------------------------------------------
__global__ void down2_kernel(const float* __restrict__ xin,
                             float* __restrict__ xs1, float* __restrict__ xs2)
{
    const int r2 = blockIdx.x;                   // 0 .. MTOK/4-1
    const int b = r2 / (TLEN / 4), t2 = r2 % (TLEN / 4);
    const size_t in0 = ((size_t)b * TLEN + (size_t)t2 * 4) * DINNER;
    const size_t o1  = ((size_t)b * (TLEN / 2) + (size_t)t2 * 2) * DINNER;
    const size_t o2  = (size_t)r2 * DINNER;
    for (int c4 = threadIdx.x; c4 < DINNER / 4; c4 += 256) {
        const int c = c4 * 4;
        const float4 v0 = *(const float4*)(xin + in0 + 0 * DINNER + c);
        const float4 v1 = *(const float4*)(xin + in0 + 1 * DINNER + c);
        const float4 v2 = *(const float4*)(xin + in0 + 2 * DINNER + c);
        const float4 v3 = *(const float4*)(xin + in0 + 3 * DINNER + c);
        float4 m01, m23, m;
        m01.x = 0.5f * (v0.x + v1.x); m01.y = 0.5f * (v0.y + v1.y);
        m01.z = 0.5f * (v0.z + v1.z); m01.w = 0.5f * (v0.w + v1.w);
        m23.x = 0.5f * (v2.x + v3.x); m23.y = 0.5f * (v2.y + v3.y);
        m23.z = 0.5f * (v2.z + v3.z); m23.w = 0.5f * (v2.w + v3.w);
        m.x = 0.5f * (m01.x + m23.x); m.y = 0.5f * (m01.y + m23.y);
        m.z = 0.5f * (m01.z + m23.z); m.w = 0.5f * (m01.w + m23.w);
        *(float4*)(xs1 + o1 + c)          = m01;
        *(float4*)(xs1 + o1 + DINNER + c) = m23;
        *(float4*)(xs2 + o2 + c)          = m;
    }
}

// ---------------------------------------------------------------------------
// Fused SSM core v2 (R7 win), output stored as half
// ---------------------------------------------------------------------------
#define SSM_SMEM (DINNER * DSTATE * 2 * 2)   // 131072

__global__ __launch_bounds__(256)
void ssm2_kernel(const float* __restrict__ X,
                 const float* __restrict__ cw,
                 const float* __restrict__ cb,
                 const float* __restrict__ xw,
                 const float* __restrict__ dtw,
                 const float* __restrict__ dtb,
                 const float* __restrict__ Dp,
                 __half* __restrict__ y, int Ts)
{
    extern __shared__ __half sh[];
    __half* s_xw  = sh;
    __half* s_dtw = sh + DINNER * DSTATE;
    __shared__ float s_wp[8][16];
    __shared__ float s_B[DSTATE];

    const int tid = threadIdx.x;
    const int lane = tid & 31, warp = tid >> 5;
    const int c0 = tid * 8;
    const int r0 = blockIdx.x * SSM_R;
    const int trow0 = r0 % Ts;

    for (int idx = tid; idx < DINNER * DSTATE; idx += 256) {
        const int c = idx >> 4, j = idx & 15;
        s_xw[idx] = __float2half(xw[c * (2 * DSTATE) + j]);
    }
    for (int idx = tid; idx < DSTATE * DINNER; idx += 256)
        s_dtw[idx] = __float2half(dtw[idx]);

    float4 cw4[8];
#pragma unroll
    for (int i = 0; i < 8; i++) cw4[i] = *(const float4*)(cw + (size_t)(c0 + i) * 4);
    float cbv[8], dtbv[8], Dv[8];
    {
        const float4 a = *(const float4*)(cb + c0);
        const float4 b = *(const float4*)(cb + c0 + 4);
        cbv[0]=a.x; cbv[1]=a.y; cbv[2]=a.z; cbv[3]=a.w;
        cbv[4]=b.x; cbv[5]=b.y; cbv[6]=b.z; cbv[7]=b.w;
        const float4 c1 = *(const float4*)(dtb + c0);
        const float4 c2 = *(const float4*)(dtb + c0 + 4);
        dtbv[0]=c1.x; dtbv[1]=c1.y; dtbv[2]=c1.z; dtbv[3]=c1.w;
        dtbv[4]=c2.x; dtbv[5]=c2.y; dtbv[6]=c2.z; dtbv[7]=c2.w;
        const float4 d1 = *(const float4*)(Dp + c0);
        const float4 d2 = *(const float4*)(Dp + c0 + 4);
        Dv[0]=d1.x; Dv[1]=d1.y; Dv[2]=d1.z; Dv[3]=d1.w;
        Dv[4]=d2.x; Dv[5]=d2.y; Dv[6]=d2.z; Dv[7]=d2.w;
    }

    auto loadrow = [&](int row, float* v) {
        const float4 a = *(const float4*)(X + (size_t)row * DINNER + c0);
        const float4 b = *(const float4*)(X + (size_t)row * DINNER + c0 + 4);
        v[0]=a.x; v[1]=a.y; v[2]=a.z; v[3]=a.w;
        v[4]=b.x; v[5]=b.y; v[6]=b.z; v[7]=b.w;
    };

    float w0[8], w1[8], w2[8], cur[8];
    if (trow0 == 0) {
#pragma unroll
        for (int i = 0; i < 8; i++) { w0[i] = 0.f; w1[i] = 0.f; w2[i] = 0.f; }
    } else {
        loadrow(r0 - 3, w0);
        loadrow(r0 - 2, w1);
        loadrow(r0 - 1, w2);
    }
    __syncthreads();

    for (int r = 0; r < SSM_R; r++) {
        const int row = r0 + r;
        loadrow(row, cur);

        float xc[8];
#pragma unroll
        for (int i = 0; i < 8; i++) {
            const float a = cbv[i] + cw4[i].x * w0[i] + cw4[i].y * w1[i]
                          + cw4[i].z * w2[i] + cw4[i].w * cur[i];
            xc[i] = siluf_(a);
        }

        float part[16];
#pragma unroll
        for (int j = 0; j < 16; j++) part[j] = 0.0f;
#pragma unroll
        for (int i = 0; i < 8; i++) {
            const __half2* p = (const __half2*)&s_xw[(c0 + i) * 16];
            const float xi = xc[i];
#pragma unroll
            for (int j2 = 0; j2 < 8; j2++) {
                const float2 f = __half22float2(p[j2]);
                part[j2 * 2]     += xi * f.x;
                part[j2 * 2 + 1] += xi * f.y;
            }
        }
#pragma unroll
        for (int j = 0; j < 16; j++)
#pragma unroll
            for (int o = 16; o; o >>= 1)
                part[j] += __shfl_xor_sync(0xffffffffu, part[j], o);
        if (lane == 0) {
#pragma unroll
            for (int j = 0; j < 16; j++) s_wp[warp][j] = part[j];
        }
        __syncthreads();
        if (tid < 16) {
            float s = 0.0f;
#pragma unroll
            for (int w = 0; w < 8; w++) s += s_wp[w][tid];
            s_B[tid] = s;
        }
        __syncthreads();

        float lo[8];
#pragma unroll
        for (int i = 0; i < 8; i++) lo[i] = dtbv[i];
#pragma unroll
        for (int j = 0; j < DSTATE; j++) {
            const float bj = s_B[j];
            const __half2* p = (const __half2*)&s_dtw[j * DINNER + c0];
#pragma unroll
            for (int i2 = 0; i2 < 4; i2++) {
                const float2 f = __half22float2(p[i2]);
                lo[i2 * 2]     += bj * f.x;
                lo[i2 * 2 + 1] += bj * f.y;
            }
        }
        float yv[8];
#pragma unroll
        for (int i = 0; i < 8; i++)
            yv[i] = xc[i] * sigmoidf_(softplusf_(lo[i])) + Dv[i] * cur[i];
        uint4 pk;
        __half2 h01 = __floats2half2_rn(yv[0], yv[1]);
        __half2 h23 = __floats2half2_rn(yv[2], yv[3]);
        __half2 h45 = __floats2half2_rn(yv[4], yv[5]);
        __half2 h67 = __floats2half2_rn(yv[6], yv[7]);
        pk.x = *(uint32_t*)&h01; pk.y = *(uint32_t*)&h23;
        pk.z = *(uint32_t*)&h45; pk.w = *(uint32_t*)&h67;
        *(uint4*)(y + (size_t)row * DINNER + c0) = pk;

#pragma unroll
        for (int i = 0; i < 8; i++) { w0[i] = w1[i]; w1[i] = w2[i]; w2[i] = cur[i]; }
        __syncthreads();
    }
}

// ---------------------------------------------------------------------------
// Linear upsample + softmax-weighted mix + ctx (half in, half out)
// ---------------------------------------------------------------------------
__global__ void mix_kernel(const __half* __restrict__ y0,
                           const __half* __restrict__ y1,
                           const __half* __restrict__ y2,
                           const float* __restrict__ sw,
                           __half* __restrict__ fused_pre_h,
                           __half* __restrict__ ctx_h)
{
    const int r = blockIdx.x;
    const int b = r >> 12, t = r & (TLEN - 1);

    const float s0 = sw[0], s1 = sw[1], s2 = sw[2];
    const float m  = fmaxf(s0, fmaxf(s1, s2));
    const float e0 = expf(s0 - m), e1 = expf(s1 - m), e2 = expf(s2 - m);
    const float inv = 1.0f / (e0 + e1 + e2);
    const float w0 = e0 * inv, w1 = e1 * inv, w2 = e2 * inv;

    float c1 = fminf(fmaxf((t + 0.5f) * 0.5f - 0.5f, 0.0f), (float)(TLEN / 2 - 1));
    int lo1 = (int)floorf(c1);
    int hi1 = min(lo1 + 1, TLEN / 2 - 1);
    float f1 = c1 - (float)lo1;

    float c2 = fminf(fmaxf((t + 0.5f) * 0.25f - 0.5f, 0.0f), (float)(TLEN / 4 - 1));
    int lo2 = (int)floorf(c2);
    int hi2 = min(lo2 + 1, TLEN / 4 - 1);
    float f2 = c2 - (float)lo2;

    const __half* p0  = y0 + (size_t)r * DINNER;
    const __half* p1a = y1 + ((size_t)(b * (TLEN / 2) + lo1)) * DINNER;
    const __half* p1b = y1 + ((size_t)(b * (TLEN / 2) + hi1)) * DINNER;
    const __half* p2a = y2 + ((size_t)(b * (TLEN / 4) + lo2)) * DINNER;
    const __half* p2b = y2 + ((size_t)(b * (TLEN / 4) + hi2)) * DINNER;

    for (int c = threadIdx.x * 2; c < DINNER; c += 512) {
        const float2 v0  = __half22float2(*(const __half2*)(p0 + c));
        const float2 a1  = __half22float2(*(const __half2*)(p1a + c));
        const float2 b1v = __half22float2(*(const __half2*)(p1b + c));
        const float2 a2  = __half22float2(*(const __half2*)(p2a + c));
        const float2 b2v = __half22float2(*(const __half2*)(p2b + c));
        const float u1x = a1.x * (1.0f - f1) + b1v.x * f1;
        const float u1y = a1.y * (1.0f - f1) + b1v.y * f1;
        const float u2x = a2.x * (1.0f - f2) + b2v.x * f2;
        const float u2y = a2.y * (1.0f - f2) + b2v.y * f2;
        const float fx = w0 * v0.x + w1 * u1x + w2 * u2x;
        const float fy = w0 * v0.y + w1 * u1y + w2 * u2y;
        *(__half2*)(fused_pre_h + (size_t)r * DINNER + c) = __floats2half2_rn(fx, fy);
        *(__half2*)(ctx_h + (size_t)r * DINNER + c) =
            __floats2half2_rn((v0.x + u1x + u2x) * (1.0f / 3.0f),
                              (v0.y + u1y + u2y) * (1.0f / 3.0f));
    }
}

// ---------------------------------------------------------------------------
// In-place LayerNorm over last dim (1024)
// ---------------------------------------------------------------------------
__global__ void ln_kernel(float* __restrict__ y,
                          const float* __restrict__ g, const float* __restrict__ b)
{
    const int r = blockIdx.x;
    const size_t base = (size_t)r * DIM;
    float v[4];
    float s = 0.0f;
#pragma unroll
    for (int i = 0; i < 4; i++) {
        v[i] = y[base + threadIdx.x + i * 256];
        s += v[i];
    }
    __shared__ float red[8];
    __shared__ float mu_sh, rs_sh;
    for (int o = 16; o; o >>= 1) s += __shfl_xor_sync(0xffffffffu, s, o);
    if ((threadIdx.x & 31) == 0) red[threadIdx.x >> 5] = s;
    __syncthreads();
    if (threadIdx.x == 0) {
        float t = 0.0f;
        for (int i = 0; i < 8; i++) t += red[i];
        mu_sh = t / (float)DIM;
    }
    __syncthreads();
    const float mu = mu_sh;
    float q = 0.0f;
#pragma unroll
    for (int i = 0; i < 4; i++) { const float d = v[i] - mu; q += d * d; }
    __syncthreads();
    for (int o = 16; o; o >>= 1) q += __shfl_xor_sync(0xffffffffu, q, o);
    if ((threadIdx.x & 31) == 0) red[threadIdx.x >> 5] = q;
    __syncthreads();
    if (threadIdx.x == 0) {
        float t = 0.0f;
        for (int i = 0; i < 8; i++) t += red[i];
        rs_sh = rsqrtf(t / (float)DIM + 1e-5f);
    }
    __syncthreads();
    const float rs = rs_sh;
#pragma unroll
    for (int i = 0; i < 4; i++) {
        const int c = threadIdx.x + i * 256;
        y[base + c] = (v[i] - mu) * rs * g[c] + b[c];
    }
}

// ---------------------------------------------------------------------------
// Launcher
// ---------------------------------------------------------------------------
extern "C" void kernel_launch(void* const* d_in, const int* in_sizes, int n_in,
                              void* d_out, int out_size)
{
    const float* x         = (const float*)d_in[0];
    const float* in_proj_w = (const float*)d_in[1];
    const float* conv_w    = (const float*)d_in[2];
    const float* conv_b    = (const float*)d_in[3];
    const float* xproj_w   = (const float*)d_in[4];
    const float* dtproj_w  = (const float*)d_in[5];
    const float* dtproj_b  = (const float*)d_in[6];
    const float* D_param   = (const float*)d_in[7];
    const float* sw        = (const float*)d_in[8];
    const float* cg_w1     = (const float*)d_in[9];
    const float* cg_w2     = (const float*)d_in[10];
    const float* out_proj  = (const float*)d_in[11];
    const float* ln_g      = (const float*)d_in[12];
    const float* ln_b      = (const float*)d_in[13];
    float* out = (float*)d_out;

    float  *xin, *xs1, *xs2;
    __half *gate_h, *x_h, *ctx_h, *h_h, *fused_h, *fusedpre_h, *wTh;
    __half *y0, *y1, *y2;
    cudaGetSymbolAddress((void**)&xin,        g_xin);
    cudaGetSymbolAddress((void**)&gate_h,     g_gate_h);
    cudaGetSymbolAddress((void**)&xs1,        g_xs1);
    cudaGetSymbolAddress((void**)&xs2,        g_xs2);
    cudaGetSymbolAddress((void**)&y0,         g_y0);
    cudaGetSymbolAddress((void**)&y1,         g_y1);
    cudaGetSymbolAddress((void**)&y2,         g_y2);
    cudaGetSymbolAddress((void**)&x_h,        g_x_h);
    cudaGetSymbolAddress((void**)&ctx_h,      g_ctx_h);
    cudaGetSymbolAddress((void**)&h_h,        g_h_h);
    cudaGetSymbolAddress((void**)&fused_h,    g_fused_h);
    cudaGetSymbolAddress((void**)&fusedpre_h, g_fusedpre_h);
    cudaGetSymbolAddress((void**)&wTh,        g_wTh);

    __half* wt_in  = wTh;
    __half* wt_cg1 = wt_in  + (size_t)DIM * 2 * DINNER;
    __half* wt_cg2 = wt_cg1 + (size_t)DINNER * (DINNER/2);
    __half* wt_out = wt_cg2 + (size_t)(DINNER/2) * DINNER;

    cudaFuncSetAttribute(tgemm_kernel<1>, cudaFuncAttributeMaxDynamicSharedMemorySize, SM_TOTALH);
    cudaFuncSetAttribute(tgemm_kernel<2>, cudaFuncAttributeMaxDynamicSharedMemorySize, SM_TOTALH);
    cudaFuncSetAttribute(tgemm_kernel<3>, cudaFuncAttributeMaxDynamicSharedMemorySize, SM_TOTALH);
    cudaFuncSetAttribute(tgemm_kernel<4>, cudaFuncAttributeMaxDynamicSharedMemorySize, SM_TOTALH);
    cudaFuncSetAttribute(ssm2_kernel,     cudaFuncAttributeMaxDynamicSharedMemorySize, SSM_SMEM);

    // 0) prepare half operands
    f2h_kernel<<<(MTOK * DIM / 4 + 255) / 256, 256>>>(x, x_h, MTOK * DIM / 4);
    transpose_kernel<<<dim3((2*DINNER)/32, DIM/32),    dim3(32, 8)>>>(in_proj_w, wt_in,  DIM,      2*DINNER);
    transpose_kernel<<<dim3((DINNER/2)/32, DINNER/32), dim3(32, 8)>>>(cg_w1,     wt_cg1, DINNER,   DINNER/2);
    transpose_kernel<<<dim3(DINNER/32, (DINNER/2)/32), dim3(32, 8)>>>(cg_w2,     wt_cg2, DINNER/2, DINNER);
    transpose_kernel<<<dim3(DIM/32, DINNER/32),        dim3(32, 8)>>>(out_proj,  wt_out, DINNER,   DIM);

    // 1) [x_in | silu(gate)] = x @ in_proj_w
    tgemm_kernel<4><<<dim3((2*DINNER)/128, MTOK/128), 256, SM_TOTALH>>>(
        x_h, wt_in, xin, MTOK, 2*DINNER, DIM, nullptr, nullptr, gate_h);

    // 2) fused downsample (x_in read once)
    down2_kernel<<<MTOK / 4, 256>>>(xin, xs1, xs2);

    // 3) per-scale fused SSM core
    ssm2_kernel<<<MTOK / SSM_R, 256, SSM_SMEM>>>(xin,
                              conv_w + 0 * DINNER * KCONV, conv_b + 0 * DINNER,
                              xproj_w + 0 * DINNER * 2 * DSTATE,
                              dtproj_w + 0 * DSTATE * DINNER,
                              dtproj_b + 0 * DINNER, D_param + 0 * DINNER,
                              y0, TLEN);
    ssm2_kernel<<<(MTOK/2) / SSM_R, 256, SSM_SMEM>>>(xs1,
                              conv_w + 1 * DINNER * KCONV, conv_b + 1 * DINNER,
                              xproj_w + 1 * DINNER * 2 * DSTATE,
                              dtproj_w + 1 * DSTATE * DINNER,
                              dtproj_b + 1 * DINNER, D_param + 1 * DINNER,
                              y1, TLEN / 2);
    ssm2_kernel<<<(MTOK/4) / SSM_R, 256, SSM_SMEM>>>(xs2,
                              conv_w + 2 * DINNER * KCONV, conv_b + 2 * DINNER,
                              xproj_w + 2 * DINNER * 2 * DSTATE,
                              dtproj_w + 2 * DSTATE * DINNER,
                              dtproj_b + 2 * DINNER, D_param + 2 * DINNER,
                              y2, TLEN / 4);

    // 4) upsample + fuse (half) + ctx (half)
    mix_kernel<<<MTOK, 256>>>(y0, y1, y2, sw, fusedpre_h, ctx_h);

    // 5) h = silu(ctx @ cg_w1) -> half
    tgemm_kernel<1><<<dim3((DINNER/2)/128, MTOK/128), 256, SM_TOTALH>>>(
        ctx_h, wt_cg1, h_h, MTOK, DINNER/2, DINNER, nullptr, nullptr, nullptr);

    // 6) fused_h = fused_pre * sigmoid(h @ cg_w2) * silu_gate
    tgemm_kernel<2><<<dim3(DINNER/128, MTOK/128), 256, SM_TOTALH>>>(
        h_h, wt_cg2, fused_h, MTOK, DINNER, DINNER/2, nullptr, fusedpre_h, gate_h);

    // 7) out = fused_h @ out_proj + residual
    tgemm_kernel<3><<<dim3(DIM/128, MTOK/128), 256, SM_TOTALH>>>(
        fused_h, wt_out, out, MTOK, DIM, DINNER, x, nullptr, nullptr);

    // 8) in-place LayerNorm
    ln_kernel<<<MTOK, 256>>>(out, ln_g, ln_b);
}

// round 14
// speedup vs baseline: 1.1456x; 1.0061x over previous
#include <cuda_runtime.h>
#include <cuda_fp16.h>
#include <math.h>
#include <stdint.h>

// ---------------------------------------------------------------------------
// Problem constants
// ---------------------------------------------------------------------------
#define BATCH     4
#define TLEN      4096
#define MTOK      (BATCH * TLEN)      // 16384 tokens
#define DIM       1024
#define DINNER    2048
#define DSTATE    16
#define KCONV     4
#define SSM_R     32

// ---------------------------------------------------------------------------
// Scratch buffers (static device globals; no allocation anywhere)
// ---------------------------------------------------------------------------
__device__ __half g_xin_h[(size_t)MTOK * DINNER];
__device__ __half g_gate_h[(size_t)MTOK * DINNER];
__device__ __half g_xs1_h[(size_t)(MTOK/2) * DINNER];
__device__ __half g_xs2_h[(size_t)(MTOK/4) * DINNER];
__device__ __half g_y0   [(size_t)MTOK     * DINNER];
__device__ __half g_y1   [(size_t)(MTOK/2) * DINNER];
__device__ __half g_y2   [(size_t)(MTOK/4) * DINNER];
__device__ __half g_fusedpre_h[(size_t)MTOK * DINNER];
__device__ __half g_x_h    [(size_t)MTOK * DIM];
__device__ __half g_ctx_h  [(size_t)MTOK * DINNER];
__device__ __half g_h_h    [(size_t)MTOK * (DINNER/2)];
__device__ __half g_fused_h[(size_t)MTOK * DINNER];
__device__ __half g_wTh  [(size_t)(DIM*2*DINNER) + (size_t)(DINNER*(DINNER/2))
                          + (size_t)((DINNER/2)*DINNER) + (size_t)(DINNER*DIM)];

// ---------------------------------------------------------------------------
// Math helpers
// ---------------------------------------------------------------------------
__device__ __forceinline__ float sigmoidf_(float x) { return 1.0f / (1.0f + expf(-x)); }
__device__ __forceinline__ float siluf_(float x)    { return x / (1.0f + expf(-x)); }
__device__ __forceinline__ float softplusf_(float x) {
    return x > 0.0f ? x + log1pf(expf(-x)) : log1pf(expf(x));
}

// ---------------------------------------------------------------------------
// PTX helpers
// ---------------------------------------------------------------------------
__device__ __forceinline__ uint32_t smem_u32(const void* p) {
    uint32_t a;
    asm("{ .reg .u64 t; cvta.to.shared.u64 t, %1; cvt.u32.u64 %0, t; }" : "=r"(a) : "l"(p));
    return a;
}
__device__ __forceinline__ void cp_async16(uint32_t saddr, const void* gaddr) {
    asm volatile("cp.async.cg.shared.global [%0], [%1], 16;"
                 :: "r"(saddr), "l"(gaddr) : "memory");
}
#define CP_COMMIT() asm volatile("cp.async.commit_group;" ::: "memory")
#define CP_WAIT(n)  asm volatile("cp.async.wait_group %0;" :: "n"(n) : "memory")

__device__ __forceinline__ void ldsm_x4(uint32_t* r, uint32_t addr) {
    asm volatile("ldmatrix.sync.aligned.m8n8.x4.shared.b16 {%0,%1,%2,%3}, [%4];"
                 : "=r"(r[0]), "=r"(r[1]), "=r"(r[2]), "=r"(r[3]) : "r"(addr));
}
__device__ __forceinline__ void mma_f16(float* d, const uint32_t* a, const uint32_t* b) {
    asm volatile(
        "mma.sync.aligned.m16n8k16.row.col.f32.f16.f16.f32 "
        "{%0,%1,%2,%3}, {%4,%5,%6,%7}, {%8,%9}, {%0,%1,%2,%3};"
        : "+f"(d[0]), "+f"(d[1]), "+f"(d[2]), "+f"(d[3])
        : "r"(a[0]), "r"(a[1]), "r"(a[2]), "r"(a[3]), "r"(b[0]), "r"(b[1]));
}

// ---------------------------------------------------------------------------
// FP16 tensor-core GEMM (exact R7-win mainloop: 128x128 tile, 8 warps 2x4,
// warp tile 64x32, 2 CTAs/SM, 3-stage cp.async).
// EPI: 1 silu->half, 2 cg-combine->half, 3 +residual->f32,
//      4 split: x_in half | silu(gate) half
// ---------------------------------------------------------------------------
#define STAGES      3
#define TILE_BYTESH 16384
#define SM_TOTALH   (STAGES * 2 * TILE_BYTESH)   // 98304

template <int EPI>
__global__ __launch_bounds__(256, 2)
void tgemm_kernel(const __half* __restrict__ A, const __half* __restrict__ Bt,
                  void* __restrict__ Cv, int M, int N, int K,
                  const float* __restrict__ aux, const __half* __restrict__ aux2h,
                  __half* __restrict__ auxh)
{
    extern __shared__ char smem[];
    const uint32_t sbase = smem_u32(smem);
    const int tid = threadIdx.x;
    const int lid = tid & 31;
    const int wid = tid >> 5;
    const int warp_m = wid & 1;
    const int warp_n = wid >> 1;
    const int bn = blockIdx.x, bm = blockIdx.y;

    const __half* Abase = A  + (size_t)bm * 128 * K;
    const __half* Bbase = Bt + (size_t)bn * 128 * K;
    const int nk = K >> 6;

    auto issue_copy = [&](int chunk, int buf) {
        const int k0 = chunk << 6;
        const int u  = tid & 7;
        const uint32_t sa = sbase + buf * (2 * TILE_BYTESH);
        const uint32_t sb = sa + TILE_BYTESH;
#pragma unroll
        for (int i = 0; i < 4; i++) {
            const int r = (tid >> 3) + i * 32;
            const uint32_t so = (uint32_t)(r * 128 + ((u ^ (r & 7)) << 4));
            cp_async16(sa + so, Abase + (size_t)r * K + k0 + u * 8);
            cp_async16(sb + so, Bbase + (size_t)r * K + k0 + u * 8);
        }
        CP_COMMIT();
    };

    float acc[4][4][4];
#pragma unroll
    for (int i = 0; i < 4; i++)
#pragma unroll
        for (int j = 0; j < 4; j++)
#pragma unroll
            for (int c = 0; c < 4; c++) acc[i][j][c] = 0.0f;

    issue_copy(0, 0);
    if (nk > 1) issue_copy(1, 1);

    for (int it = 0; it < nk; ++it) {
        if (it + 2 < nk) { issue_copy(it + 2, (it + 2) % STAGES); CP_WAIT(2); }
        else if (it + 1 < nk) { CP_WAIT(1); }
        else { CP_WAIT(0); }
        __syncthreads();

        const uint32_t a_s = sbase + (it % STAGES) * (2 * TILE_BYTESH);
        const uint32_t b_s = a_s + TILE_BYTESH;

#pragma unroll
        for (int ks = 0; ks < 4; ks++) {
            const int ub = ks * 2;
            uint32_t af[4][4];
#pragma unroll
            for (int mf = 0; mf < 4; mf++) {
                const int row  = warp_m * 64 + mf * 16 + (lid & 15);
                const int unit = ub + (lid >> 4);
                ldsm_x4(af[mf], a_s + (uint32_t)(row * 128 + ((unit ^ (row & 7)) << 4)));
            }
            uint32_t bf[4][2];
#pragma unroll
            for (int p = 0; p < 2; p++) {
                const int row  = warp_n * 32 + p * 16 + ((lid >> 4) & 1) * 8 + (lid & 7);
                const int unit = ub + ((lid >> 3) & 1);
                uint32_t t[4];
                ldsm_x4(t, b_s + (uint32_t)(row * 128 + ((unit ^ (row & 7)) << 4)));
                bf[p * 2][0] = t[0]; bf[p * 2][1] = t[1];
                bf[p * 2 + 1][0] = t[2]; bf[p * 2 + 1][1] = t[3];
            }
#pragma unroll
            for (int mf = 0; mf < 4; mf++)
#pragma unroll
                for (int nf = 0; nf < 4; nf++)
                    mma_f16(acc[mf][nf], af[mf], bf[nf]);
        }
        __syncthreads();
    }

    // Epilogue
#pragma unroll
    for (int mf = 0; mf < 4; mf++)
#pragma unroll
        for (int nf = 0; nf < 4; nf++)
#pragma unroll
            for (int hh = 0; hh < 2; hh++) {
                const int row = bm * 128 + warp_m * 64 + mf * 16 + (lid >> 2) + hh * 8;
                const int col = bn * 128 + warp_n * 32 + nf * 8 + (lid & 3) * 2;
                float2 v = make_float2(acc[mf][nf][hh * 2], acc[mf][nf][hh * 2 + 1]);
                const size_t idx = (size_t)row * N + col;
                if (EPI == 1) {
                    *(__half2*)((__half*)Cv + idx) =
                        __floats2half2_rn(siluf_(v.x), siluf_(v.y));
                } else if (EPI == 2) {
                    const float2 f  = __half22float2(*(const __half2*)(aux2h + idx));
                    const float2 gt = __half22float2(*(const __half2*)(auxh + idx));
                    const float ox = f.x * sigmoidf_(v.x) * gt.x;
                    const float oy = f.y * sigmoidf_(v.y) * gt.y;
                    *(__half2*)((__half*)Cv + idx) = __floats2half2_rn(ox, oy);
                } else if (EPI == 3) {
                    const float2 rr = *(const float2*)(aux + idx);
                    v.x += rr.x; v.y += rr.y;
                    *(float2*)((float*)Cv + idx) = v;
                } else { // EPI == 4: split x_in half | silu(gate) half
                    if (col < DINNER) {
                        *(__half2*)((__half*)Cv + (size_t)row * DINNER + col) =
                            __floats2half2_rn(v.x, v.y);
                    } else {
                        *(__half2*)(auxh + (size_t)row * DINNER + (col - DINNER)) =
                            __floats2half2_rn(siluf_(v.x), siluf_(v.y));
                    }
                }
            }
}

// ---------------------------------------------------------------------------
// fp32 -> fp16 convert
// ---------------------------------------------------------------------------
__global__ void f2h_kernel(const float* __restrict__ in, __half* __restrict__ out,
                           int n4)
{
    const int i = blockIdx.x * 256 + threadIdx.x;
    if (i < n4) {
        const float4 v = *(const float4*)(in + (size_t)i * 4);
        ((__half2*)out)[(size_t)i * 2]     = __floats2half2_rn(v.x, v.y);
        ((__half2*)out)[(size_t)i * 2 + 1] = __floats2half2_rn(v.z, v.w);
    }
}

// ---------------------------------------------------------------------------
// Weight transpose: in[K,N] fp32 -> out[N,K] fp16
// ---------------------------------------------------------------------------
__global__ void transpose_kernel(const float* __restrict__ in, __half* __restrict__ out,
                                 int K, int N)
{
    __shared__ float t[32][33];
    const int n0 = blockIdx.x * 32, k0 = blockIdx.y * 32;
    const int tx = threadIdx.x, ty = threadIdx.y;
#pragma unroll
    for (int i = 0; i < 32; i += 8)
        t[ty + i][tx] = in[(size_t)(k0 + ty + i) * N + n0 + tx];
    __syncthreads();
#pragma unroll
    for (int i = 0; i < 32; i += 8)
        out[(size_t)(n0 + ty + i) * K + k0 + tx] = __float2half(t[tx][ty + i]);
}

// ---------------------------------------------------------------------------
// Fused downsample (half in / half out): 4 rows read once -> 2 xs1 + 1 xs2
// ---------------------------------------------------------------------------
__global__ void down2_kernel(const __half* __restrict__ xin,
                             __half* __restrict__ xs1, __half* __restrict__ xs2)
{
    const int r2 = blockIdx.x;                   // 0 .. MTOK/4-1
    const int b = r2 / (TLEN / 4), t2 = r2 % (TLEN / 4);
    const size_t in0 = ((size_t)b * TLEN + (size_t)t2 * 4) * DINNER;
    const size_t o1  = ((size_t)b * (TLEN / 2) + (size_t)t2 * 2) * DINNER;
    const size_t o2  = (size_t)r2 * DINNER;
    for (int c2 = threadIdx.x; c2 < DINNER / 2; c2 += 256) {
        const int c = c2 * 2;
        const float2 v0 = __half22float2(*(const __half2*)(xin + in0 + 0 * DINNER + c));
        const float2 v1 = __half22float2(*(const __half2*)(xin + in0 + 1 * DINNER + c));
        const float2 v2 = __half22float2(*(const __half2*)(xin + in0 + 2 * DINNER + c));
        const float2 v3 = __half22float2(*(const __half2*)(xin + in0 + 3 * DINNER + c));
        const float m01x = 0.5f * (v0.x + v1.x), m01y = 0.5f * (v0.y + v1.y);
        const float m23x = 0.5f * (v2.x + v3.x), m23y = 0.5f * (v2.y + v3.y);
        *(__half2*)(xs1 + o1 + c)          = __floats2half2_rn(m01x, m01y);
        *(__half2*)(xs1 + o1 + DINNER + c) = __floats2half2_rn(m23x, m23y);
        *(__half2*)(xs2 + o2 + c) =
            __floats2half2_rn(0.5f * (m01x + m23x), 0.5f * (m01y + m23y));
    }
}

// ---------------------------------------------------------------------------
// Fused SSM core v2 (R7 win): X half, y half; smem weights (half)
// ---------------------------------------------------------------------------
#define SSM_SMEM (DINNER * DSTATE * 2 * 2)   // 131072

__global__ __launch_bounds__(256)
void ssm2_kernel(const __half* __restrict__ X,
                 const float* __restrict__ cw,
                 const float* __restrict__ cb,
                 const float* __restrict__ xw,
                 const float* __restrict__ dtw,
                 const float* __restrict__ dtb,
                 const float* __restrict__ Dp,
                 __half* __restrict__ y, int Ts)
{
    extern __shared__ __half sh[];
    __half* s_xw  = sh;
    __half* s_dtw = sh + DINNER * DSTATE;
    __shared__ float s_wp[8][16];
    __shared__ float s_B[DSTATE];

    const int tid = threadIdx.x;
    const int lane = tid & 31, warp = tid >> 5;
    const int c0 = tid * 8;
    const int r0 = blockIdx.x * SSM_R;
    const int trow0 = r0 % Ts;

    for (int idx = tid; idx < DINNER * DSTATE; idx += 256) {
        const int c = idx >> 4, j = idx & 15;
        s_xw[idx] = __float2half(xw[c * (2 * DSTATE) + j]);
    }
    for (int idx = tid; idx < DSTATE * DINNER; idx += 256)
        s_dtw[idx] = __float2half(dtw[idx]);

    float4 cw4[8];
#pragma unroll
    for (int i = 0; i < 8; i++) cw4[i] = *(const float4*)(cw + (size_t)(c0 + i) * 4);
    float cbv[8], dtbv[8], Dv[8];
    {
        const float4 a = *(const float4*)(cb + c0);
        const float4 b = *(const float4*)(cb + c0 + 4);
        cbv[0]=a.x; cbv[1]=a.y; cbv[2]=a.z; cbv[3]=a.w;
        cbv[4]=b.x; cbv[5]=b.y; cbv[6]=b.z; cbv[7]=b.w;
        const float4 c1 = *(const float4*)(dtb + c0);
        const float4 c2 = *(const float4*)(dtb + c0 + 4);
        dtbv[0]=c1.x; dtbv[1]=c1.y; dtbv[2]=c1.z; dtbv[3]=c1.w;
        dtbv[4]=c2.x; dtbv[5]=c2.y; dtbv[6]=c2.z; dtbv[7]=c2.w;
        const float4 d1 = *(const float4*)(Dp + c0);
        const float4 d2 = *(const float4*)(Dp + c0 + 4);
        Dv[0]=d1.x; Dv[1]=d1.y; Dv[2]=d1.z; Dv[3]=d1.w;
        Dv[4]=d2.x; Dv[5]=d2.y; Dv[6]=d2.z; Dv[7]=d2.w;
    }

    auto loadrow = [&](int row, float* v) {
        const uint4 pk = *(const uint4*)(X + (size_t)row * DINNER + c0);
        const float2 f0 = __half22float2(*(const __half2*)&pk.x);
        const float2 f1 = __half22float2(*(const __half2*)&pk.y);
        const float2 f2 = __half22float2(*(const __half2*)&pk.z);
        const float2 f3 = __half22float2(*(const __half2*)&pk.w);
        v[0]=f0.x; v[1]=f0.y; v[2]=f1.x; v[3]=f1.y;
        v[4]=f2.x; v[5]=f2.y; v[6]=f3.x; v[7]=f3.y;
    };

    float w0[8], w1[8], w2[8], cur[8];
    if (trow0 == 0) {
#pragma unroll
        for (int i = 0; i < 8; i++) { w0[i] = 0.f; w1[i] = 0.f; w2[i] = 0.f; }
    } else {
        loadrow(r0 - 3, w0);
        loadrow(r0 - 2, w1);
        loadrow(r0 - 1, w2);
    }
    __syncthreads();

    for (int r = 0; r < SSM_R; r++) {
        const int row = r0 + r;
        loadrow(row, cur);

        float xc[8];
#pragma unroll
        for (int i = 0; i < 8; i++) {
            const float a = cbv[i] + cw4[i].x * w0[i] + cw4[i].y * w1[i]
                          + cw4[i].z * w2[i] + cw4[i].w * cur[i];
            xc[i] = siluf_(a);
        }

        float part[16];
#pragma unroll
        for (int j = 0; j < 16; j++) part[j] = 0.0f;
#pragma unroll
        for (int i = 0; i < 8; i++) {
            const __half2* p = (const __half2*)&s_xw[(c0 + i) * 16];
            const float xi = xc[i];
#pragma unroll
            for (int j2 = 0; j2 < 8; j2++) {
                const float2 f = __half22float2(p[j2]);
                part[j2 * 2]     += xi * f.x;
                part[j2 * 2 + 1] += xi * f.y;
            }
        }
#pragma unroll
        for (int j = 0; j < 16; j++)
#pragma unroll
            for (int o = 16; o; o >>= 1)
                part[j] += __shfl_xor_sync(0xffffffffu, part[j], o);
        if (lane == 0) {
#pragma unroll
            for (int j = 0; j < 16; j++) s_wp[warp][j] = part[j];
        }
        __syncthreads();
        if (tid < 16) {
            float s = 0.0f;
#pragma unroll
            for (int w = 0; w < 8; w++) s += s_wp[w][tid];
            s_B[tid] = s;
        }
        __syncthreads();

        float lo[8];
#pragma unroll
        for (int i = 0; i < 8; i++) lo[i] = dtbv[i];
#pragma unroll
        for (int j = 0; j < DSTATE; j++) {
            const float bj = s_B[j];
            const __half2* p = (const __half2*)&s_dtw[j * DINNER + c0];
#pragma unroll
            for (int i2 = 0; i2 < 4; i2++) {
                const float2 f = __half22float2(p[i2]);
                lo[i2 * 2]     += bj * f.x;
                lo[i2 * 2 + 1] += bj * f.y;
            }
        }
        float yv[8];
#pragma unroll
        for (int i = 0; i < 8; i++)
            yv[i] = xc[i] * sigmoidf_(softplusf_(lo[i])) + Dv[i] * cur[i];
        uint4 pk;
        __half2 h01 = __floats2half2_rn(yv[0], yv[1]);
        __half2 h23 = __floats2half2_rn(yv[2], yv[3]);
        __half2 h45 = __floats2half2_rn(yv[4], yv[5]);
        __half2 h67 = __floats2half2_rn(yv[6], yv[7]);
        pk.x = *(uint32_t*)&h01; pk.y = *(uint32_t*)&h23;
        pk.z = *(uint32_t*)&h45; pk.w = *(uint32_t*)&h67;
        *(uint4*)(y + (size_t)row * DINNER + c0) = pk;

#pragma unroll
        for (int i = 0; i < 8; i++) { w0[i] = w1[i]; w1[i] = w2[i]; w2[i] = cur[i]; }
        __syncthreads();
    }
}

// ---------------------------------------------------------------------------
// Linear upsample + softmax-weighted mix + ctx (half in, half out)
// ---------------------------------------------------------------------------
__global__ void mix_kernel(const __half* __restrict__ y0,
                           const __half* __restrict__ y1,
                           const __half* __restrict__ y2,
                           const float* __restrict__ sw,
                           __half* __restrict__ fused_pre_h,
                           __half* __restrict__ ctx_h)
{
    const int r = blockIdx.x;
    const int b = r >> 12, t = r & (TLEN - 1);

    const float s0 = sw[0], s1 = sw[1], s2 = sw[2];
    const float m  = fmaxf(s0, fmaxf(s1, s2));
    const float e0 = expf(s0 - m), e1 = expf(s1 - m), e2 = expf(s2 - m);
    const float inv = 1.0f / (e0 + e1 + e2);
    const float w0 = e0 * inv, w1 = e1 * inv, w2 = e2 * inv;

    float c1 = fminf(fmaxf((t + 0.5f) * 0.5f - 0.5f, 0.0f), (float)(TLEN / 2 - 1));
    int lo1 = (int)floorf(c1);
    int hi1 = min(lo1 + 1, TLEN / 2 - 1);
    float f1 = c1 - (float)lo1;

    float c2 = fminf(fmaxf((t + 0.5f) * 0.25f - 0.5f, 0.0f), (float)(TLEN / 4 - 1));
    int lo2 = (int)floorf(c2);
    int hi2 = min(lo2 + 1, TLEN / 4 - 1);
    float f2 = c2 - (float)lo2;

    const __half* p0  = y0 + (size_t)r * DINNER;
    const __half* p1a = y1 + ((size_t)(b * (TLEN / 2) + lo1)) * DINNER;
    const __half* p1b = y1 + ((size_t)(b * (TLEN / 2) + hi1)) * DINNER;
    const __half* p2a = y2 + ((size_t)(b * (TLEN / 4) + lo2)) * DINNER;
    const __half* p2b = y2 + ((size_t)(b * (TLEN / 4) + hi2)) * DINNER;

    for (int c = threadIdx.x * 2; c < DINNER; c += 512) {
        const float2 v0  = __half22float2(*(const __half2*)(p0 + c));
        const float2 a1  = __half22float2(*(const __half2*)(p1a + c));
        const float2 b1v = __half22float2(*(const __half2*)(p1b + c));
        const float2 a2  = __half22float2(*(const __half2*)(p2a + c));
        const float2 b2v = __half22float2(*(const __half2*)(p2b + c));
        const float u1x = a1.x * (1.0f - f1) + b1v.x * f1;
        const float u1y = a1.y * (1.0f - f1) + b1v.y * f1;
        const float u2x = a2.x * (1.0f - f2) + b2v.x * f2;
        const float u2y = a2.y * (1.0f - f2) + b2v.y * f2;
        const float fx = w0 * v0.x + w1 * u1x + w2 * u2x;
        const float fy = w0 * v0.y + w1 * u1y + w2 * u2y;
        *(__half2*)(fused_pre_h + (size_t)r * DINNER + c) = __floats2half2_rn(fx, fy);
        *(__half2*)(ctx_h + (size_t)r * DINNER + c) =
            __floats2half2_rn((v0.x + u1x + u2x) * (1.0f / 3.0f),
                              (v0.y + u1y + u2y) * (1.0f / 3.0f));
    }
}

// ---------------------------------------------------------------------------
// In-place LayerNorm over last dim (1024)
// ---------------------------------------------------------------------------
__global__ void ln_kernel(float* __restrict__ y,
                          const float* __restrict__ g, const float* __restrict__ b)
{
    const int r = blockIdx.x;
    const size_t base = (size_t)r * DIM;
    float v[4];
    float s = 0.0f;
#pragma unroll
    for (int i = 0; i < 4; i++) {
        v[i] = y[base + threadIdx.x + i * 256];
        s += v[i];
    }
    __shared__ float red[8];
    __shared__ float mu_sh, rs_sh;
    for (int o = 16; o; o >>= 1) s += __shfl_xor_sync(0xffffffffu, s, o);
    if ((threadIdx.x & 31) == 0) red[threadIdx.x >> 5] = s;
    __syncthreads();
    if (threadIdx.x == 0) {
        float t = 0.0f;
        for (int i = 0; i < 8; i++) t += red[i];
        mu_sh = t / (float)DIM;
    }
    __syncthreads();
    const float mu = mu_sh;
    float q = 0.0f;
#pragma unroll
    for (int i = 0; i < 4; i++) { const float d = v[i] - mu; q += d * d; }
    __syncthreads();
    for (int o = 16; o; o >>= 1) q += __shfl_xor_sync(0xffffffffu, q, o);
    if ((threadIdx.x & 31) == 0) red[threadIdx.x >> 5] = q;
    __syncthreads();
    if (threadIdx.x == 0) {
        float t = 0.0f;
        for (int i = 0; i < 8; i++) t += red[i];
        rs_sh = rsqrtf(t / (float)DIM + 1e-5f);
    }
    __syncthreads();
    const float rs = rs_sh;
#pragma unroll
    for (int i = 0; i < 4; i++) {
        const int c = threadIdx.x + i * 256;
        y[base + c] = (v[i] - mu) * rs * g[c] + b[c];
    }
}

// ---------------------------------------------------------------------------
// Launcher
// ---------------------------------------------------------------------------
extern "C" void kernel_launch(void* const* d_in, const int* in_sizes, int n_in,
                              void* d_out, int out_size)
{
    const float* x         = (const float*)d_in[0];
    const float* in_proj_w = (const float*)d_in[1];
    const float* conv_w    = (const float*)d_in[2];
    const float* conv_b    = (const float*)d_in[3];
    const float* xproj_w   = (const float*)d_in[4];
    const float* dtproj_w  = (const float*)d_in[5];
    const float* dtproj_b  = (const float*)d_in[6];
    const float* D_param   = (const float*)d_in[7];
    const float* sw        = (const float*)d_in[8];
    const float* cg_w1     = (const float*)d_in[9];
    const float* cg_w2     = (const float*)d_in[10];
    const float* out_proj  = (const float*)d_in[11];
    const float* ln_g      = (const float*)d_in[12];
    const float* ln_b      = (const float*)d_in[13];
    float* out = (float*)d_out;

    __half *xin_h, *gate_h, *xs1_h, *xs2_h, *x_h, *ctx_h, *h_h;
    __half *fused_h, *fusedpre_h, *wTh, *y0, *y1, *y2;
    cudaGetSymbolAddress((void**)&xin_h,      g_xin_h);
    cudaGetSymbolAddress((void**)&gate_h,     g_gate_h);
    cudaGetSymbolAddress((void**)&xs1_h,      g_xs1_h);
    cudaGetSymbolAddress((void**)&xs2_h,      g_xs2_h);
    cudaGetSymbolAddress((void**)&y0,         g_y0);
    cudaGetSymbolAddress((void**)&y1,         g_y1);
    cudaGetSymbolAddress((void**)&y2,         g_y2);
    cudaGetSymbolAddress((void**)&x_h,        g_x_h);
    cudaGetSymbolAddress((void**)&ctx_h,      g_ctx_h);
    cudaGetSymbolAddress((void**)&h_h,        g_h_h);
    cudaGetSymbolAddress((void**)&fused_h,    g_fused_h);
    cudaGetSymbolAddress((void**)&fusedpre_h, g_fusedpre_h);
    cudaGetSymbolAddress((void**)&wTh,        g_wTh);

    __half* wt_in  = wTh;
    __half* wt_cg1 = wt_in  + (size_t)DIM * 2 * DINNER;
    __half* wt_cg2 = wt_cg1 + (size_t)DINNER * (DINNER/2);
    __half* wt_out = wt_cg2 + (size_t)(DINNER/2) * DINNER;

    cudaFuncSetAttribute(tgemm_kernel<1>, cudaFuncAttributeMaxDynamicSharedMemorySize, SM_TOTALH);
    cudaFuncSetAttribute(tgemm_kernel<2>, cudaFuncAttributeMaxDynamicSharedMemorySize, SM_TOTALH);
    cudaFuncSetAttribute(tgemm_kernel<3>, cudaFuncAttributeMaxDynamicSharedMemorySize, SM_TOTALH);
    cudaFuncSetAttribute(tgemm_kernel<4>, cudaFuncAttributeMaxDynamicSharedMemorySize, SM_TOTALH);
    cudaFuncSetAttribute(ssm2_kernel,     cudaFuncAttributeMaxDynamicSharedMemorySize, SSM_SMEM);

    // 0) prepare half operands
    f2h_kernel<<<(MTOK * DIM / 4 + 255) / 256, 256>>>(x, x_h, MTOK * DIM / 4);
    transpose_kernel<<<dim3((2*DINNER)/32, DIM/32),    dim3(32, 8)>>>(in_proj_w, wt_in,  DIM,      2*DINNER);
    transpose_kernel<<<dim3((DINNER/2)/32, DINNER/32), dim3(32, 8)>>>(cg_w1,     wt_cg1, DINNER,   DINNER/2);
    transpose_kernel<<<dim3(DINNER/32, (DINNER/2)/32), dim3(32, 8)>>>(cg_w2,     wt_cg2, DINNER/2, DINNER);
    transpose_kernel<<<dim3(DIM/32, DINNER/32),        dim3(32, 8)>>>(out_proj,  wt_out, DINNER,   DIM);

    // 1) [x_in | silu(gate)] = x @ in_proj_w  (both halves stored as half)
    tgemm_kernel<4><<<dim3((2*DINNER)/128, MTOK/128), 256, SM_TOTALH>>>(
        x_h, wt_in, xin_h, MTOK, 2*DINNER, DIM, nullptr, nullptr, gate_h);

    // 2) fused downsample (x_in read once, half)
    down2_kernel<<<MTOK / 4, 256>>>(xin_h, xs1_h, xs2_h);

    // 3) per-scale fused SSM core (half I/O)
    ssm2_kernel<<<MTOK / SSM_R, 256, SSM_SMEM>>>(xin_h,
                              conv_w + 0 * DINNER * KCONV, conv_b + 0 * DINNER,
                              xproj_w + 0 * DINNER * 2 * DSTATE,
                              dtproj_w + 0 * DSTATE * DINNER,
                              dtproj_b + 0 * DINNER, D_param + 0 * DINNER,
                              y0, TLEN);
    ssm2_kernel<<<(MTOK/2) / SSM_R, 256, SSM_SMEM>>>(xs1_h,
                              conv_w + 1 * DINNER * KCONV, conv_b + 1 * DINNER,
                              xproj_w + 1 * DINNER * 2 * DSTATE,
                              dtproj_w + 1 * DSTATE * DINNER,
                              dtproj_b + 1 * DINNER, D_param + 1 * DINNER,
                              y1, TLEN / 2);
    ssm2_kernel<<<(MTOK/4) / SSM_R, 256, SSM_SMEM>>>(xs2_h,
                              conv_w + 2 * DINNER * KCONV, conv_b + 2 * DINNER,
                              xproj_w + 2 * DINNER * 2 * DSTATE,
                              dtproj_w + 2 * DSTATE * DINNER,
                              dtproj_b + 2 * DINNER, D_param + 2 * DINNER,
                              y2, TLEN / 4);

    // 4) upsample + fuse (half) + ctx (half)
    mix_kernel<<<MTOK, 256>>>(y0, y1, y2, sw, fusedpre_h, ctx_h);

    // 5) h = silu(ctx @ cg_w1) -> half
    tgemm_kernel<1><<<dim3((DINNER/2)/128, MTOK/128), 256, SM_TOTALH>>>(
        ctx_h, wt_cg1, h_h, MTOK, DINNER/2, DINNER, nullptr, nullptr, nullptr);

    // 6) fused_h = fused_pre * sigmoid(h @ cg_w2) * silu_gate
    tgemm_kernel<2><<<dim3(DINNER/128, MTOK/128), 256, SM_TOTALH>>>(
        h_h, wt_cg2, fused_h, MTOK, DINNER, DINNER/2, nullptr, fusedpre_h, gate_h);

    // 7) out = fused_h @ out_proj + residual
    tgemm_kernel<3><<<dim3(DIM/128, MTOK/128), 256, SM_TOTALH>>>(
        fused_h, wt_out, out, MTOK, DIM, DINNER, x, nullptr, nullptr);

    // 8) in-place LayerNorm
    ln_kernel<<<MTOK, 256>>>(out, ln_g, ln_b);
}